// round 4
// baseline (speedup 1.0000x reference)
#include <cuda_runtime.h>
#include <math.h>

#define NPOS 4096
#define FULLM 0xffffffffu

// ---------------- scratch (static device globals; no allocation) -------------
__device__ float g_qkv[NPOS * 576];   // (pos, 576) pos-major
__device__ float g_o  [NPOS * 192];   // (pos, 192) pos-major
__device__ float g_x2 [192 * NPOS];   // (C, pos)  channel-major
__device__ float g_m  [768 * NPOS];   // (768, pos)
__device__ float g_sums[2 * 192];     // per-channel sum / sumsq
__device__ float g_mult[192];         // scale*gamma/rms

// ---------------- tf32 helpers ------------------------------------------------
__device__ __forceinline__ float tf32_round(float x) {
    unsigned u;
    asm("cvt.rna.tf32.f32 %0, %1;" : "=r"(u) : "f"(x));
    return __uint_as_float(u);
}
__device__ __forceinline__ void mma_tf32(float* d, const unsigned* a, const unsigned* b) {
    asm volatile(
        "mma.sync.aligned.m16n8k8.row.col.f32.tf32.tf32.f32 "
        "{%0,%1,%2,%3},{%4,%5,%6,%7},{%8,%9},{%0,%1,%2,%3};"
        : "+f"(d[0]), "+f"(d[1]), "+f"(d[2]), "+f"(d[3])
        : "r"(a[0]), "r"(a[1]), "r"(a[2]), "r"(a[3]), "r"(b[0]), "r"(b[1]));
}

// ---------------- per-channel sum & sumsq over 4096 spatial elems ------------
__global__ void colstats_kernel(const float* __restrict__ x) {
    int c = blockIdx.x;
    const float* p = x + c * NPOS;
    float s = 0.f, s2 = 0.f;
    for (int i = threadIdx.x; i < NPOS; i += 256) {
        float v = p[i];
        s += v;
        s2 = fmaf(v, v, s2);
    }
    __shared__ float sh0[256], sh1[256];
    sh0[threadIdx.x] = s; sh1[threadIdx.x] = s2;
    __syncthreads();
    for (int o = 128; o > 0; o >>= 1) {
        if (threadIdx.x < o) {
            sh0[threadIdx.x] += sh0[threadIdx.x + o];
            sh1[threadIdx.x] += sh1[threadIdx.x + o];
        }
        __syncthreads();
    }
    if (threadIdx.x == 0) {
        g_sums[c]       = sh0[0];
        g_sums[192 + c] = sh1[0];
    }
}

// ---------------- tiny MLP -> per-channel multiplier scale*gamma/rms ---------
__global__ void gamma_kernel(const float* __restrict__ w1, const float* __restrict__ b1,
                             const float* __restrict__ w2, const float* __restrict__ b2,
                             const float* __restrict__ scale) {
    __shared__ float stats[192];
    __shared__ float h[384];
    const int t = threadIdx.x, warp = t >> 5, lane = t & 31;
    if (t < 192) stats[t] = g_sums[t] * (1.0f / 4096.0f);
    __syncthreads();

    #pragma unroll
    for (int g = 0; g < 8; g++) {
        int ob = warp * 32 + g * 4;
        float acc0 = 0.f, acc1 = 0.f, acc2 = 0.f, acc3 = 0.f;
        #pragma unroll
        for (int j = 0; j < 6; j++) {
            float sv = stats[lane + j * 32];
            acc0 = fmaf(sv, w1[(ob + 0) * 192 + lane + j * 32], acc0);
            acc1 = fmaf(sv, w1[(ob + 1) * 192 + lane + j * 32], acc1);
            acc2 = fmaf(sv, w1[(ob + 2) * 192 + lane + j * 32], acc2);
            acc3 = fmaf(sv, w1[(ob + 3) * 192 + lane + j * 32], acc3);
        }
        #pragma unroll
        for (int off = 16; off; off >>= 1) {
            acc0 += __shfl_xor_sync(FULLM, acc0, off);
            acc1 += __shfl_xor_sync(FULLM, acc1, off);
            acc2 += __shfl_xor_sync(FULLM, acc2, off);
            acc3 += __shfl_xor_sync(FULLM, acc3, off);
        }
        if (lane == 0) {
            h[ob + 0] = fmaxf(acc0 + b1[ob + 0], 0.f);
            h[ob + 1] = fmaxf(acc1 + b1[ob + 1], 0.f);
            h[ob + 2] = fmaxf(acc2 + b1[ob + 2], 0.f);
            h[ob + 3] = fmaxf(acc3 + b1[ob + 3], 0.f);
        }
    }
    __syncthreads();

    if (warp < 6) {
        #pragma unroll
        for (int g = 0; g < 8; g++) {
            int ob = warp * 32 + g * 4;
            float acc0 = 0.f, acc1 = 0.f, acc2 = 0.f, acc3 = 0.f;
            #pragma unroll
            for (int j = 0; j < 12; j++) {
                float hv = h[lane + j * 32];
                acc0 = fmaf(hv, w2[(ob + 0) * 384 + lane + j * 32], acc0);
                acc1 = fmaf(hv, w2[(ob + 1) * 384 + lane + j * 32], acc1);
                acc2 = fmaf(hv, w2[(ob + 2) * 384 + lane + j * 32], acc2);
                acc3 = fmaf(hv, w2[(ob + 3) * 384 + lane + j * 32], acc3);
            }
            #pragma unroll
            for (int off = 16; off; off >>= 1) {
                acc0 += __shfl_xor_sync(FULLM, acc0, off);
                acc1 += __shfl_xor_sync(FULLM, acc1, off);
                acc2 += __shfl_xor_sync(FULLM, acc2, off);
                acc3 += __shfl_xor_sync(FULLM, acc3, off);
            }
            if (lane == 0) {
                #pragma unroll
                for (int u = 0; u < 4; u++) {
                    float a = (u == 0 ? acc0 : u == 1 ? acc1 : u == 2 ? acc2 : acc3) + b2[ob + u];
                    float gamma = 1.f / (1.f + expf(-a));
                    float rms = sqrtf(g_sums[192 + ob + u] * (1.0f / 4096.0f) + 1e-6f);
                    g_mult[ob + u] = scale[ob + u] * gamma / rms;
                }
            }
        }
    }
    __syncthreads();
    if (t < 192) { g_sums[t] = 0.f; g_sums[192 + t] = 0.f; }
}

// ---------------- GEMM v4 (tf32 tensor cores, 3xTF32 split) -------------------
// out = epi(W(Co,Ci) @ X(Ci,N) + bias). Block 64(m) x 128(n), 256 thr = 8 warps
// in 2(m)x4(n). Warp tile 32x32 via m16n8k8. K-tile 16, reg-prefetch pipeline.
// XN:   X stored as (N,Ci)
// EPI:  0 none, 1 exact gelu, 2 +res (res in (Co,N))
// WS:   scale W k-entries by g_mult[k] at load (adaRMSNorm fold)
// STATS: accumulate per-channel sum/sumsq of outputs into g_sums (atomicAdd)
// OUTNCO: write (N,Co) instead of (Co,N)
template <int CI, bool XN, int EPI, bool WS, bool STATS, bool OUTNCO>
__global__ void __launch_bounds__(256)
gemm_kernel(const float* __restrict__ W, const float* __restrict__ X,
            const float* __restrict__ bias, const float* __restrict__ res,
            float* __restrict__ out, int Co, int N) {
    __shared__ float sWb[16][72], sWs[16][72];     // [k][m] big / small
    __shared__ float sXb[16][136], sXs[16][136];   // [k][n] big / small
    const int NK = CI / 16;

    const int bn = blockIdx.x * 128;
    const int bm = blockIdx.y * 64;
    const int tid = threadIdx.x;
    const int warp = tid >> 5, lane = tid & 31;
    const int gid = lane >> 2, tig = lane & 3;
    const int wmb = (warp >> 2) * 32;   // warp m offset within block tile
    const int wnb = (warp & 3) * 32;    // warp n offset

    // staging roles
    const int wk = tid & 15, wm = tid >> 4;
    float regW[4];
    float4 regX4[2];
    float regXs[8];

    float d[2][4][4];   // [m-tile 16][n-tile 8][frag]
    #pragma unroll
    for (int mt = 0; mt < 2; mt++)
        #pragma unroll
        for (int j = 0; j < 4; j++)
            #pragma unroll
            for (int e = 0; e < 4; e++) d[mt][j][e] = 0.f;

    auto loadTile = [&](int kk) {
        float gm = WS ? g_mult[kk + wk] : 1.f;
        #pragma unroll
        for (int r = 0; r < 4; r++)
            regW[r] = W[(size_t)(bm + wm + r * 16) * CI + kk + wk] * gm;
        if (XN) {
            #pragma unroll
            for (int r = 0; r < 8; r++)
                regXs[r] = X[(size_t)(bn + wm + r * 16) * CI + kk + wk];
        } else {
            #pragma unroll
            for (int i = 0; i < 2; i++) {
                int fi = tid + i * 256;
                int k = fi >> 5, n4 = fi & 31;
                regX4[i] = *(const float4*)(X + (size_t)(kk + k) * N + bn + n4 * 4);
            }
        }
    };
    auto storeTile = [&]() {
        #pragma unroll
        for (int r = 0; r < 4; r++) {
            float big = tf32_round(regW[r]);
            sWb[wk][wm + r * 16] = big;
            sWs[wk][wm + r * 16] = tf32_round(regW[r] - big);
        }
        if (XN) {
            #pragma unroll
            for (int r = 0; r < 8; r++) {
                float big = tf32_round(regXs[r]);
                sXb[wk][wm + r * 16] = big;
                sXs[wk][wm + r * 16] = tf32_round(regXs[r] - big);
            }
        } else {
            #pragma unroll
            for (int i = 0; i < 2; i++) {
                int fi = tid + i * 256;
                int k = fi >> 5, n4 = fi & 31;
                float4 v = regX4[i];
                float4 bg = make_float4(tf32_round(v.x), tf32_round(v.y),
                                        tf32_round(v.z), tf32_round(v.w));
                float4 sm = make_float4(tf32_round(v.x - bg.x), tf32_round(v.y - bg.y),
                                        tf32_round(v.z - bg.z), tf32_round(v.w - bg.w));
                *(float4*)&sXb[k][n4 * 4] = bg;
                *(float4*)&sXs[k][n4 * 4] = sm;
            }
        }
    };

    loadTile(0);
    storeTile();
    __syncthreads();

    #pragma unroll 1
    for (int t = 0; t < NK; t++) {
        if (t + 1 < NK) loadTile((t + 1) * 16);
        #pragma unroll
        for (int ks = 0; ks < 16; ks += 8) {
            unsigned Ab[2][4], As[2][4];
            #pragma unroll
            for (int mt = 0; mt < 2; mt++) {
                int mc = wmb + 16 * mt + gid;
                Ab[mt][0] = __float_as_uint(sWb[ks + tig][mc]);
                Ab[mt][1] = __float_as_uint(sWb[ks + tig][mc + 8]);
                Ab[mt][2] = __float_as_uint(sWb[ks + tig + 4][mc]);
                Ab[mt][3] = __float_as_uint(sWb[ks + tig + 4][mc + 8]);
                As[mt][0] = __float_as_uint(sWs[ks + tig][mc]);
                As[mt][1] = __float_as_uint(sWs[ks + tig][mc + 8]);
                As[mt][2] = __float_as_uint(sWs[ks + tig + 4][mc]);
                As[mt][3] = __float_as_uint(sWs[ks + tig + 4][mc + 8]);
            }
            #pragma unroll
            for (int j = 0; j < 4; j++) {
                int nc = wnb + 8 * j + gid;
                unsigned Bb[2] = { __float_as_uint(sXb[ks + tig][nc]),
                                   __float_as_uint(sXb[ks + tig + 4][nc]) };
                unsigned Bs[2] = { __float_as_uint(sXs[ks + tig][nc]),
                                   __float_as_uint(sXs[ks + tig + 4][nc]) };
                #pragma unroll
                for (int mt = 0; mt < 2; mt++) {
                    mma_tf32(d[mt][j], Ab[mt], Bb);
                    mma_tf32(d[mt][j], As[mt], Bb);
                    mma_tf32(d[mt][j], Ab[mt], Bs);
                }
            }
        }
        __syncthreads();
        if (t + 1 < NK) {
            storeTile();
            __syncthreads();
        }
    }

    // ---- epilogue ----
    const int gn0 = bn + wnb + 2 * tig;
    #pragma unroll
    for (int mt = 0; mt < 2; mt++) {
        #pragma unroll
        for (int half = 0; half < 2; half++) {
            int m = bm + wmb + 16 * mt + gid + 8 * half;
            float bv = bias[m];
            float v[8];
            #pragma unroll
            for (int j = 0; j < 4; j++) {
                v[2 * j]     = d[mt][j][2 * half]     + bv;
                v[2 * j + 1] = d[mt][j][2 * half + 1] + bv;
            }
            if (EPI == 1) {
                #pragma unroll
                for (int e = 0; e < 8; e++) {
                    float u = v[e];
                    v[e] = u * 0.5f * (1.f + erff(u * 0.70710678118654752f));
                }
            }
            if (EPI == 2) {
                #pragma unroll
                for (int j = 0; j < 4; j++) {
                    float2 r2 = *(const float2*)&res[(size_t)m * N + gn0 + 8 * j];
                    v[2 * j] += r2.x; v[2 * j + 1] += r2.y;
                }
            }
            if (STATS) {
                float ls = 0.f, ls2 = 0.f;
                #pragma unroll
                for (int e = 0; e < 8; e++) { ls += v[e]; ls2 = fmaf(v[e], v[e], ls2); }
                ls  += __shfl_xor_sync(FULLM, ls, 1);  ls  += __shfl_xor_sync(FULLM, ls, 2);
                ls2 += __shfl_xor_sync(FULLM, ls2, 1); ls2 += __shfl_xor_sync(FULLM, ls2, 2);
                if (tig == 0) {
                    atomicAdd(&g_sums[m], ls);
                    atomicAdd(&g_sums[192 + m], ls2);
                }
            }
            if (!OUTNCO) {
                #pragma unroll
                for (int j = 0; j < 4; j++)
                    *(float2*)&out[(size_t)m * N + gn0 + 8 * j] = make_float2(v[2 * j], v[2 * j + 1]);
            } else {
                #pragma unroll
                for (int j = 0; j < 4; j++) {
                    out[(size_t)(gn0 + 8 * j)     * Co + m] = v[2 * j];
                    out[(size_t)(gn0 + 8 * j + 1) * Co + m] = v[2 * j + 1];
                }
            }
        }
    }
}

// ---------------- 3D neighborhood attention (tiled) ---------------------------
#define KV_STRIDE 36
__device__ __forceinline__ void load_kv_tile(float* sKV, const float* __restrict__ src,
                                             int Bd, int Bh, int Bw, int tid) {
    #pragma unroll
    for (int it = 0; it < 16; it++) {
        int i = tid + it * 256;
        int row = i >> 3, g = i & 7;
        int rd = row >> 6, rh = (row >> 3) & 7, rw = row & 7;
        int gpos = ((Bd + rd) << 8) + ((Bh + rh) << 4) + (Bw + rw);
        float4 val = *(const float4*)(src + (size_t)gpos * 576 + g * 4);
        int q = g >> 1, c2 = (g & 1) * 4;
        *(float4*)&sKV[row * KV_STRIDE + ((q ^ (row & 3)) << 3) + c2] = val;
    }
}

__global__ void __launch_bounds__(256) attn_kernel(const float* __restrict__ qkv,
                                                   float* __restrict__ o) {
    extern __shared__ float sKV[];
    const int tile = blockIdx.x, head = blockIdx.y;
    const int Td = ((tile >> 4) & 3) * 4, Th = ((tile >> 2) & 3) * 4, Tw = (tile & 3) * 4;
    const int Bd = min(max(Td - 2, 0), 8);
    const int Bh = min(max(Th - 2, 0), 8);
    const int Bw = min(max(Tw - 2, 0), 8);

    const int tid = threadIdx.x;
    const int quarter = tid & 3, vox = tid >> 2;
    const int aw = vox & 3, ah = (vox >> 2) & 3, ad = vox >> 4;
    const int vd = Td + ad, vh = Th + ah, vw = Tw + aw;
    const int gv = (vd << 8) + (vh << 4) + vw;
    const int ld = min(max(vd - 2, 0), 11) - Bd;
    const int lh = min(max(vh - 2, 0), 11) - Bh;
    const int lw = min(max(vw - 2, 0), 11) - Bw;
    const int rbase = ld * 64 + lh * 8 + lw;
    const int lane = tid & 31;

    float q[8];
    {
        const float* qp = qkv + (size_t)gv * 576 + head * 32 + quarter * 8;
        #pragma unroll
        for (int c = 0; c < 8; c++) q[c] = qp[c] * 0.17677669529663687f;
    }

    load_kv_tile(sKV, qkv + 192 + head * 32, Bd, Bh, Bw, tid);
    __syncthreads();

    float sc[32];
    #pragma unroll
    for (int i = 0; i < 32; i++) sc[i] = -1e30f;

    #pragma unroll
    for (int j = 0; j < 125; j++) {
        const int a = j / 25, b = (j / 5) % 5, c5 = j % 5;
        int row = rbase + a * 64 + b * 8 + c5;
        int cb = row * KV_STRIDE + ((quarter ^ (row & 3)) << 3);
        float4 k0 = *(const float4*)&sKV[cb];
        float4 k1 = *(const float4*)&sKV[cb + 4];
        float p = q[0] * k0.x;
        p = fmaf(q[1], k0.y, p); p = fmaf(q[2], k0.z, p); p = fmaf(q[3], k0.w, p);
        p = fmaf(q[4], k1.x, p); p = fmaf(q[5], k1.y, p);
        p = fmaf(q[6], k1.z, p); p = fmaf(q[7], k1.w, p);
        p += __shfl_xor_sync(FULLM, p, 1);
        p += __shfl_xor_sync(FULLM, p, 2);
        if ((j & 3) == quarter) sc[j >> 2] = p;
    }

    float mx = -1e30f;
    #pragma unroll
    for (int i = 0; i < 32; i++) mx = fmaxf(mx, sc[i]);
    mx = fmaxf(mx, __shfl_xor_sync(FULLM, mx, 1));
    mx = fmaxf(mx, __shfl_xor_sync(FULLM, mx, 2));
    float tot = 0.f;
    #pragma unroll
    for (int i = 0; i < 32; i++) { sc[i] = __expf(sc[i] - mx); tot += sc[i]; }
    tot += __shfl_xor_sync(FULLM, tot, 1);
    tot += __shfl_xor_sync(FULLM, tot, 2);
    float inv = 1.f / tot;

    __syncthreads();
    load_kv_tile(sKV, qkv + 384 + head * 32, Bd, Bh, Bw, tid);
    __syncthreads();

    float o8[8] = {0.f, 0.f, 0.f, 0.f, 0.f, 0.f, 0.f, 0.f};
    #pragma unroll
    for (int j = 0; j < 125; j++) {
        const int a = j / 25, b = (j / 5) % 5, c5 = j % 5;
        float p = __shfl_sync(FULLM, sc[j >> 2], (lane & ~3) | (j & 3));
        int row = rbase + a * 64 + b * 8 + c5;
        int cb = row * KV_STRIDE + ((quarter ^ (row & 3)) << 3);
        float4 v0 = *(const float4*)&sKV[cb];
        float4 v1 = *(const float4*)&sKV[cb + 4];
        o8[0] = fmaf(p, v0.x, o8[0]); o8[1] = fmaf(p, v0.y, o8[1]);
        o8[2] = fmaf(p, v0.z, o8[2]); o8[3] = fmaf(p, v0.w, o8[3]);
        o8[4] = fmaf(p, v1.x, o8[4]); o8[5] = fmaf(p, v1.y, o8[5]);
        o8[6] = fmaf(p, v1.z, o8[6]); o8[7] = fmaf(p, v1.w, o8[7]);
    }
    float* op = o + (size_t)gv * 192 + head * 32 + quarter * 8;
    #pragma unroll
    for (int c = 0; c < 8; c++) op[c] = o8[c] * inv;
}

// ---------------- orchestration ----------------------------------------------
extern "C" void kernel_launch(void* const* d_in, const int* in_sizes, int n_in,
                              void* d_out, int out_size) {
    const float* x      = (const float*)d_in[0];
    const float* scale1 = (const float*)d_in[1];
    const float* n1_w1  = (const float*)d_in[2];
    const float* n1_b1  = (const float*)d_in[3];
    const float* n1_w2  = (const float*)d_in[4];
    const float* n1_b2  = (const float*)d_in[5];
    const float* qkv_w  = (const float*)d_in[6];
    const float* qkv_b  = (const float*)d_in[7];
    const float* proj_w = (const float*)d_in[8];
    const float* proj_b = (const float*)d_in[9];
    const float* scale2 = (const float*)d_in[10];
    const float* n2_w1  = (const float*)d_in[11];
    const float* n2_b1  = (const float*)d_in[12];
    const float* n2_w2  = (const float*)d_in[13];
    const float* n2_b2  = (const float*)d_in[14];
    const float* mlp_w1 = (const float*)d_in[15];
    const float* mlp_b1 = (const float*)d_in[16];
    const float* mlp_w2 = (const float*)d_in[17];
    const float* mlp_b2 = (const float*)d_in[18];
    float* out = (float*)d_out;

    float *qkv, *ob, *x2, *mb;
    cudaGetSymbolAddress((void**)&qkv, g_qkv);
    cudaGetSymbolAddress((void**)&ob,  g_o);
    cudaGetSymbolAddress((void**)&x2,  g_x2);
    cudaGetSymbolAddress((void**)&mb,  g_m);

    cudaFuncSetAttribute(attn_kernel, cudaFuncAttributeMaxDynamicSharedMemorySize,
                         512 * KV_STRIDE * 4);

    // ---- stage A ----
    colstats_kernel<<<192, 256>>>(x);
    gamma_kernel<<<1, 384>>>(n1_w1, n1_b1, n1_w2, n1_b2, scale1);  // zeroes g_sums after

    // qkv: (576,192)@(192,4096) -> (4096,576) pos-major
    gemm_kernel<192, false, 0, true, false, true><<<dim3(32, 9), 256>>>(
        qkv_w, x, qkv_b, nullptr, qkv, 576, NPOS);

    // attention -> O (4096,192) pos-major
    attn_kernel<<<dim3(64, 6), 256, 512 * KV_STRIDE * 4>>>(qkv, ob);

    // proj + residual + fused stage-B colstats: x2 (C,N)
    gemm_kernel<192, true, 2, false, true, false><<<dim3(32, 3), 256>>>(
        proj_w, ob, proj_b, x, x2, 192, NPOS);

    // ---- stage B ----
    gamma_kernel<<<1, 384>>>(n2_w1, n2_b1, n2_w2, n2_b2, scale2);

    // mlp1 + gelu: (768,192)@(192,4096) -> (768,4096)
    gemm_kernel<192, false, 1, true, false, false><<<dim3(32, 12), 256>>>(
        mlp_w1, x2, mlp_b1, nullptr, mb, 768, NPOS);

    // mlp2 + residual -> final output (C,N) == (1,192,16,16,16)
    gemm_kernel<768, false, 2, false, false, false><<<dim3(32, 3), 256>>>(
        mlp_w2, mb, mlp_b2, x2, out, 192, NPOS);
}

// round 5
// speedup vs baseline: 1.2190x; 1.2190x over previous
#include <cuda_runtime.h>
#include <cuda_fp16.h>
#include <math.h>

#define NPOS 4096
#define FULLM 0xffffffffu

// ---------------- scratch (static device globals; no allocation) -------------
__device__ float g_qkv[NPOS * 576];   // (pos, 576) pos-major
__device__ float g_o  [NPOS * 192];   // (pos, 192) pos-major
__device__ float g_x2 [192 * NPOS];   // (C, pos)  channel-major
__device__ float g_m  [768 * NPOS];   // (768, pos)
__device__ float g_sums[2 * 192];     // per-channel sum / sumsq (zero-init)
__device__ float g_mult[192];         // scale*gamma/rms
__device__ float g_h[384];            // norm-MLP hidden

// ---------------- tf32 helpers ------------------------------------------------
__device__ __forceinline__ float tf32_round(float x) {
    unsigned u;
    asm("cvt.rna.tf32.f32 %0, %1;" : "=r"(u) : "f"(x));
    return __uint_as_float(u);
}
__device__ __forceinline__ void mma_tf32(float* d, const unsigned* a, const unsigned* b) {
    asm volatile(
        "mma.sync.aligned.m16n8k8.row.col.f32.tf32.tf32.f32 "
        "{%0,%1,%2,%3},{%4,%5,%6,%7},{%8,%9},{%0,%1,%2,%3};"
        : "+f"(d[0]), "+f"(d[1]), "+f"(d[2]), "+f"(d[3])
        : "r"(a[0]), "r"(a[1]), "r"(a[2]), "r"(a[3]), "r"(b[0]), "r"(b[1]));
}

// ---------------- per-channel sum & sumsq over 4096 spatial elems ------------
__global__ void colstats_kernel(const float* __restrict__ x) {
    int c = blockIdx.x;
    const float* p = x + c * NPOS;
    float s = 0.f, s2 = 0.f;
    for (int i = threadIdx.x; i < NPOS; i += 256) {
        float v = p[i];
        s += v;
        s2 = fmaf(v, v, s2);
    }
    __shared__ float sh0[256], sh1[256];
    sh0[threadIdx.x] = s; sh1[threadIdx.x] = s2;
    __syncthreads();
    for (int o = 128; o > 0; o >>= 1) {
        if (threadIdx.x < o) {
            sh0[threadIdx.x] += sh0[threadIdx.x + o];
            sh1[threadIdx.x] += sh1[threadIdx.x + o];
        }
        __syncthreads();
    }
    if (threadIdx.x == 0) {
        g_sums[c]       = sh0[0];
        g_sums[192 + c] = sh1[0];
    }
}

// ---------------- norm-MLP layer 1: h = relu(W1 @ stats + b1) ----------------
// grid 24 x 128 threads: 4 warps x 4 outputs each, coalesced dot over 192.
__global__ void gamma1_kernel(const float* __restrict__ w1, const float* __restrict__ b1) {
    const int warp = threadIdx.x >> 5, lane = threadIdx.x & 31;
    const int ob = blockIdx.x * 16 + warp * 4;
    float a0 = 0.f, a1 = 0.f, a2 = 0.f, a3 = 0.f;
    #pragma unroll
    for (int j = 0; j < 6; j++) {
        float sv = g_sums[lane + j * 32] * (1.0f / 4096.0f);
        a0 = fmaf(sv, w1[(ob + 0) * 192 + lane + j * 32], a0);
        a1 = fmaf(sv, w1[(ob + 1) * 192 + lane + j * 32], a1);
        a2 = fmaf(sv, w1[(ob + 2) * 192 + lane + j * 32], a2);
        a3 = fmaf(sv, w1[(ob + 3) * 192 + lane + j * 32], a3);
    }
    #pragma unroll
    for (int off = 16; off; off >>= 1) {
        a0 += __shfl_xor_sync(FULLM, a0, off);
        a1 += __shfl_xor_sync(FULLM, a1, off);
        a2 += __shfl_xor_sync(FULLM, a2, off);
        a3 += __shfl_xor_sync(FULLM, a3, off);
    }
    if (lane == 0) {
        g_h[ob + 0] = fmaxf(a0 + b1[ob + 0], 0.f);
        g_h[ob + 1] = fmaxf(a1 + b1[ob + 1], 0.f);
        g_h[ob + 2] = fmaxf(a2 + b1[ob + 2], 0.f);
        g_h[ob + 3] = fmaxf(a3 + b1[ob + 3], 0.f);
    }
}

// ---------------- norm-MLP layer 2 -> g_mult; zeroes g_sums -------------------
// grid 12 x 128 threads: 4 warps x 4 outputs each, dot over 384.
__global__ void gamma2_kernel(const float* __restrict__ w2, const float* __restrict__ b2,
                              const float* __restrict__ scale) {
    const int warp = threadIdx.x >> 5, lane = threadIdx.x & 31;
    const int ob = blockIdx.x * 16 + warp * 4;
    float a0 = 0.f, a1 = 0.f, a2 = 0.f, a3 = 0.f;
    #pragma unroll
    for (int j = 0; j < 12; j++) {
        float hv = g_h[lane + j * 32];
        a0 = fmaf(hv, w2[(ob + 0) * 384 + lane + j * 32], a0);
        a1 = fmaf(hv, w2[(ob + 1) * 384 + lane + j * 32], a1);
        a2 = fmaf(hv, w2[(ob + 2) * 384 + lane + j * 32], a2);
        a3 = fmaf(hv, w2[(ob + 3) * 384 + lane + j * 32], a3);
    }
    #pragma unroll
    for (int off = 16; off; off >>= 1) {
        a0 += __shfl_xor_sync(FULLM, a0, off);
        a1 += __shfl_xor_sync(FULLM, a1, off);
        a2 += __shfl_xor_sync(FULLM, a2, off);
        a3 += __shfl_xor_sync(FULLM, a3, off);
    }
    if (lane == 0) {
        #pragma unroll
        for (int u = 0; u < 4; u++) {
            float a = (u == 0 ? a0 : u == 1 ? a1 : u == 2 ? a2 : a3) + b2[ob + u];
            float gamma = 1.f / (1.f + expf(-a));
            float rms = sqrtf(g_sums[192 + ob + u] * (1.0f / 4096.0f) + 1e-6f);
            g_mult[ob + u] = scale[ob + u] * gamma / rms;
            g_sums[ob + u] = 0.f;           // reset for next STATS producer
            g_sums[192 + ob + u] = 0.f;
        }
    }
}

// ---------------- GEMM v4 (tf32 tensor cores, 3xTF32 split) -------------------
template <int CI, bool XN, int EPI, bool WS, bool STATS, bool OUTNCO>
__global__ void __launch_bounds__(256)
gemm_kernel(const float* __restrict__ W, const float* __restrict__ X,
            const float* __restrict__ bias, const float* __restrict__ res,
            float* __restrict__ out, int Co, int N) {
    __shared__ float sWb[16][72], sWs[16][72];     // [k][m] big / small
    __shared__ float sXb[16][136], sXs[16][136];   // [k][n] big / small
    const int NK = CI / 16;

    const int bn = blockIdx.x * 128;
    const int bm = blockIdx.y * 64;
    const int tid = threadIdx.x;
    const int warp = tid >> 5, lane = tid & 31;
    const int gid = lane >> 2, tig = lane & 3;
    const int wmb = (warp >> 2) * 32;
    const int wnb = (warp & 3) * 32;

    const int wk = tid & 15, wm = tid >> 4;
    float regW[4];
    float4 regX4[2];
    float regXs[8];

    float d[2][4][4];
    #pragma unroll
    for (int mt = 0; mt < 2; mt++)
        #pragma unroll
        for (int j = 0; j < 4; j++)
            #pragma unroll
            for (int e = 0; e < 4; e++) d[mt][j][e] = 0.f;

    auto loadTile = [&](int kk) {
        float gm = WS ? g_mult[kk + wk] : 1.f;
        #pragma unroll
        for (int r = 0; r < 4; r++)
            regW[r] = W[(size_t)(bm + wm + r * 16) * CI + kk + wk] * gm;
        if (XN) {
            #pragma unroll
            for (int r = 0; r < 8; r++)
                regXs[r] = X[(size_t)(bn + wm + r * 16) * CI + kk + wk];
        } else {
            #pragma unroll
            for (int i = 0; i < 2; i++) {
                int fi = tid + i * 256;
                int k = fi >> 5, n4 = fi & 31;
                regX4[i] = *(const float4*)(X + (size_t)(kk + k) * N + bn + n4 * 4);
            }
        }
    };
    auto storeTile = [&]() {
        #pragma unroll
        for (int r = 0; r < 4; r++) {
            float big = tf32_round(regW[r]);
            sWb[wk][wm + r * 16] = big;
            sWs[wk][wm + r * 16] = tf32_round(regW[r] - big);
        }
        if (XN) {
            #pragma unroll
            for (int r = 0; r < 8; r++) {
                float big = tf32_round(regXs[r]);
                sXb[wk][wm + r * 16] = big;
                sXs[wk][wm + r * 16] = tf32_round(regXs[r] - big);
            }
        } else {
            #pragma unroll
            for (int i = 0; i < 2; i++) {
                int fi = tid + i * 256;
                int k = fi >> 5, n4 = fi & 31;
                float4 v = regX4[i];
                float4 bg = make_float4(tf32_round(v.x), tf32_round(v.y),
                                        tf32_round(v.z), tf32_round(v.w));
                float4 sm = make_float4(tf32_round(v.x - bg.x), tf32_round(v.y - bg.y),
                                        tf32_round(v.z - bg.z), tf32_round(v.w - bg.w));
                *(float4*)&sXb[k][n4 * 4] = bg;
                *(float4*)&sXs[k][n4 * 4] = sm;
            }
        }
    };

    loadTile(0);
    storeTile();
    __syncthreads();

    #pragma unroll 1
    for (int t = 0; t < NK; t++) {
        if (t + 1 < NK) loadTile((t + 1) * 16);
        #pragma unroll
        for (int ks = 0; ks < 16; ks += 8) {
            unsigned Ab[2][4], As[2][4];
            #pragma unroll
            for (int mt = 0; mt < 2; mt++) {
                int mc = wmb + 16 * mt + gid;
                Ab[mt][0] = __float_as_uint(sWb[ks + tig][mc]);
                Ab[mt][1] = __float_as_uint(sWb[ks + tig][mc + 8]);
                Ab[mt][2] = __float_as_uint(sWb[ks + tig + 4][mc]);
                Ab[mt][3] = __float_as_uint(sWb[ks + tig + 4][mc + 8]);
                As[mt][0] = __float_as_uint(sWs[ks + tig][mc]);
                As[mt][1] = __float_as_uint(sWs[ks + tig][mc + 8]);
                As[mt][2] = __float_as_uint(sWs[ks + tig + 4][mc]);
                As[mt][3] = __float_as_uint(sWs[ks + tig + 4][mc + 8]);
            }
            #pragma unroll
            for (int j = 0; j < 4; j++) {
                int nc = wnb + 8 * j + gid;
                unsigned Bb[2] = { __float_as_uint(sXb[ks + tig][nc]),
                                   __float_as_uint(sXb[ks + tig + 4][nc]) };
                unsigned Bs[2] = { __float_as_uint(sXs[ks + tig][nc]),
                                   __float_as_uint(sXs[ks + tig + 4][nc]) };
                #pragma unroll
                for (int mt = 0; mt < 2; mt++) {
                    mma_tf32(d[mt][j], Ab[mt], Bb);
                    mma_tf32(d[mt][j], As[mt], Bb);
                    mma_tf32(d[mt][j], Ab[mt], Bs);
                }
            }
        }
        __syncthreads();
        if (t + 1 < NK) {
            storeTile();
            __syncthreads();
        }
    }

    // ---- epilogue ----
    const int gn0 = bn + wnb + 2 * tig;
    #pragma unroll
    for (int mt = 0; mt < 2; mt++) {
        #pragma unroll
        for (int half = 0; half < 2; half++) {
            int m = bm + wmb + 16 * mt + gid + 8 * half;
            float bv = bias[m];
            float v[8];
            #pragma unroll
            for (int j = 0; j < 4; j++) {
                v[2 * j]     = d[mt][j][2 * half]     + bv;
                v[2 * j + 1] = d[mt][j][2 * half + 1] + bv;
            }
            if (EPI == 1) {
                #pragma unroll
                for (int e = 0; e < 8; e++) {
                    float u = v[e];
                    v[e] = u * 0.5f * (1.f + erff(u * 0.70710678118654752f));
                }
            }
            if (EPI == 2) {
                #pragma unroll
                for (int j = 0; j < 4; j++) {
                    float2 r2 = *(const float2*)&res[(size_t)m * N + gn0 + 8 * j];
                    v[2 * j] += r2.x; v[2 * j + 1] += r2.y;
                }
            }
            if (STATS) {
                float ls = 0.f, ls2 = 0.f;
                #pragma unroll
                for (int e = 0; e < 8; e++) { ls += v[e]; ls2 = fmaf(v[e], v[e], ls2); }
                ls  += __shfl_xor_sync(FULLM, ls, 1);  ls  += __shfl_xor_sync(FULLM, ls, 2);
                ls2 += __shfl_xor_sync(FULLM, ls2, 1); ls2 += __shfl_xor_sync(FULLM, ls2, 2);
                if (tig == 0) {
                    atomicAdd(&g_sums[m], ls);
                    atomicAdd(&g_sums[192 + m], ls2);
                }
            }
            if (!OUTNCO) {
                #pragma unroll
                for (int j = 0; j < 4; j++)
                    *(float2*)&out[(size_t)m * N + gn0 + 8 * j] = make_float2(v[2 * j], v[2 * j + 1]);
            } else {
                #pragma unroll
                for (int j = 0; j < 4; j++) {
                    out[(size_t)(gn0 + 8 * j)     * Co + m] = v[2 * j];
                    out[(size_t)(gn0 + 8 * j + 1) * Co + m] = v[2 * j + 1];
                }
            }
        }
    }
}

// ---------------- 3D neighborhood attention (tiled, fp16 K/V in smem) ---------
// block = (4x4x4 voxel tile, one head). 256 threads = 64 voxels x 4 ch-quarters.
// 8^3 neighborhood-union K and V both staged in fp16 (64 KB dynamic smem).
// Row layout: 32 halves = 64 B, stride 16 half2 (no pad); adjacent rows fall in
// disjoint 16-bank windows, so paired-lane phases are conflict-free.
__global__ void __launch_bounds__(256) attn_kernel(const float* __restrict__ qkv,
                                                   float* __restrict__ o) {
    extern __shared__ __align__(16) half2 sKV[];   // sK[8192] then sV[8192]
    half2* sK = sKV;
    half2* sV = sKV + 8192;

    const int tile = blockIdx.x, head = blockIdx.y;
    const int Td = ((tile >> 4) & 3) * 4, Th = ((tile >> 2) & 3) * 4, Tw = (tile & 3) * 4;
    const int Bd = min(max(Td - 2, 0), 8);
    const int Bh = min(max(Th - 2, 0), 8);
    const int Bw = min(max(Tw - 2, 0), 8);

    const int tid = threadIdx.x;

    // ---- stage K and V (fp32 -> fp16) ----
    #pragma unroll
    for (int it = 0; it < 16; it++) {
        int i = tid + it * 256;
        int row = i >> 3, g = i & 7;           // 512 rows x 8 groups of 4 ch
        int rd = row >> 6, rh = (row >> 3) & 7, rw = row & 7;
        int gpos = ((Bd + rd) << 8) + ((Bh + rh) << 4) + (Bw + rw);
        const float* base = qkv + (size_t)gpos * 576 + head * 32 + g * 4;
        float4 kv = *(const float4*)(base + 192);
        float4 vv = *(const float4*)(base + 384);
        sK[row * 16 + g * 2]     = __floats2half2_rn(kv.x, kv.y);
        sK[row * 16 + g * 2 + 1] = __floats2half2_rn(kv.z, kv.w);
        sV[row * 16 + g * 2]     = __floats2half2_rn(vv.x, vv.y);
        sV[row * 16 + g * 2 + 1] = __floats2half2_rn(vv.z, vv.w);
    }

    const int quarter = tid & 3, vox = tid >> 2;
    const int aw = vox & 3, ah = (vox >> 2) & 3, ad = vox >> 4;
    const int vd = Td + ad, vh = Th + ah, vw = Tw + aw;
    const int gv = (vd << 8) + (vh << 4) + vw;
    const int ld = min(max(vd - 2, 0), 11) - Bd;
    const int lh = min(max(vh - 2, 0), 11) - Bh;
    const int lw = min(max(vw - 2, 0), 11) - Bw;
    const int rbase = ld * 64 + lh * 8 + lw;
    const int lane = tid & 31;

    // Q (8 channels per thread), pre-scaled
    float q[8];
    {
        const float* qp = qkv + (size_t)gv * 576 + head * 32 + quarter * 8;
        #pragma unroll
        for (int c = 0; c < 8; c++) q[c] = qp[c] * 0.17677669529663687f;
    }
    __syncthreads();

    // ---- pass 1: scores ----
    float sc[32];
    #pragma unroll
    for (int i = 0; i < 32; i++) sc[i] = -1e30f;

    #pragma unroll
    for (int j = 0; j < 125; j++) {
        const int a = j / 25, b = (j / 5) % 5, c5 = j % 5;
        int row = rbase + a * 64 + b * 8 + c5;
        uint4 kk = *(const uint4*)(sK + row * 16 + quarter * 4);
        float2 f0 = __half22float2(*reinterpret_cast<half2*>(&kk.x));
        float2 f1 = __half22float2(*reinterpret_cast<half2*>(&kk.y));
        float2 f2 = __half22float2(*reinterpret_cast<half2*>(&kk.z));
        float2 f3 = __half22float2(*reinterpret_cast<half2*>(&kk.w));
        float p = q[0] * f0.x;
        p = fmaf(q[1], f0.y, p); p = fmaf(q[2], f1.x, p); p = fmaf(q[3], f1.y, p);
        p = fmaf(q[4], f2.x, p); p = fmaf(q[5], f2.y, p);
        p = fmaf(q[6], f3.x, p); p = fmaf(q[7], f3.y, p);
        p += __shfl_xor_sync(FULLM, p, 1);
        p += __shfl_xor_sync(FULLM, p, 2);
        if ((j & 3) == quarter) sc[j >> 2] = p;
    }

    // ---- softmax across 4-lane quarter groups ----
    float mx = -1e30f;
    #pragma unroll
    for (int i = 0; i < 32; i++) mx = fmaxf(mx, sc[i]);
    mx = fmaxf(mx, __shfl_xor_sync(FULLM, mx, 1));
    mx = fmaxf(mx, __shfl_xor_sync(FULLM, mx, 2));
    float tot = 0.f;
    #pragma unroll
    for (int i = 0; i < 32; i++) { sc[i] = __expf(sc[i] - mx); tot += sc[i]; }
    tot += __shfl_xor_sync(FULLM, tot, 1);
    tot += __shfl_xor_sync(FULLM, tot, 2);
    float inv = 1.f / tot;

    // ---- pass 2: weighted sum of V ----
    float o8[8] = {0.f, 0.f, 0.f, 0.f, 0.f, 0.f, 0.f, 0.f};
    #pragma unroll
    for (int j = 0; j < 125; j++) {
        const int a = j / 25, b = (j / 5) % 5, c5 = j % 5;
        float p = __shfl_sync(FULLM, sc[j >> 2], (lane & ~3) | (j & 3));
        int row = rbase + a * 64 + b * 8 + c5;
        uint4 vvp = *(const uint4*)(sV + row * 16 + quarter * 4);
        float2 f0 = __half22float2(*reinterpret_cast<half2*>(&vvp.x));
        float2 f1 = __half22float2(*reinterpret_cast<half2*>(&vvp.y));
        float2 f2 = __half22float2(*reinterpret_cast<half2*>(&vvp.z));
        float2 f3 = __half22float2(*reinterpret_cast<half2*>(&vvp.w));
        o8[0] = fmaf(p, f0.x, o8[0]); o8[1] = fmaf(p, f0.y, o8[1]);
        o8[2] = fmaf(p, f1.x, o8[2]); o8[3] = fmaf(p, f1.y, o8[3]);
        o8[4] = fmaf(p, f2.x, o8[4]); o8[5] = fmaf(p, f2.y, o8[5]);
        o8[6] = fmaf(p, f3.x, o8[6]); o8[7] = fmaf(p, f3.y, o8[7]);
    }
    float* op = o + (size_t)gv * 192 + head * 32 + quarter * 8;
    #pragma unroll
    for (int c = 0; c < 8; c++) op[c] = o8[c] * inv;
}

// ---------------- orchestration ----------------------------------------------
extern "C" void kernel_launch(void* const* d_in, const int* in_sizes, int n_in,
                              void* d_out, int out_size) {
    const float* x      = (const float*)d_in[0];
    const float* scale1 = (const float*)d_in[1];
    const float* n1_w1  = (const float*)d_in[2];
    const float* n1_b1  = (const float*)d_in[3];
    const float* n1_w2  = (const float*)d_in[4];
    const float* n1_b2  = (const float*)d_in[5];
    const float* qkv_w  = (const float*)d_in[6];
    const float* qkv_b  = (const float*)d_in[7];
    const float* proj_w = (const float*)d_in[8];
    const float* proj_b = (const float*)d_in[9];
    const float* scale2 = (const float*)d_in[10];
    const float* n2_w1  = (const float*)d_in[11];
    const float* n2_b1  = (const float*)d_in[12];
    const float* n2_w2  = (const float*)d_in[13];
    const float* n2_b2  = (const float*)d_in[14];
    const float* mlp_w1 = (const float*)d_in[15];
    const float* mlp_b1 = (const float*)d_in[16];
    const float* mlp_w2 = (const float*)d_in[17];
    const float* mlp_b2 = (const float*)d_in[18];
    float* out = (float*)d_out;

    float *qkv, *ob, *x2, *mb;
    cudaGetSymbolAddress((void**)&qkv, g_qkv);
    cudaGetSymbolAddress((void**)&ob,  g_o);
    cudaGetSymbolAddress((void**)&x2,  g_x2);
    cudaGetSymbolAddress((void**)&mb,  g_m);

    cudaFuncSetAttribute(attn_kernel, cudaFuncAttributeMaxDynamicSharedMemorySize, 65536);

    // ---- stage A ----
    colstats_kernel<<<192, 256>>>(x);
    gamma1_kernel<<<24, 128>>>(n1_w1, n1_b1);
    gamma2_kernel<<<12, 128>>>(n1_w2, n1_b2, scale1);   // zeroes g_sums

    // qkv: (576,192)@(192,4096) -> (4096,576) pos-major
    gemm_kernel<192, false, 0, true, false, true><<<dim3(32, 9), 256>>>(
        qkv_w, x, qkv_b, nullptr, qkv, 576, NPOS);

    // attention -> O (4096,192) pos-major
    attn_kernel<<<dim3(64, 6), 256, 65536>>>(qkv, ob);

    // proj + residual + fused stage-B colstats: x2 (C,N)
    gemm_kernel<192, true, 2, false, true, false><<<dim3(32, 3), 256>>>(
        proj_w, ob, proj_b, x, x2, 192, NPOS);

    // ---- stage B ----
    gamma1_kernel<<<24, 128>>>(n2_w1, n2_b1);
    gamma2_kernel<<<12, 128>>>(n2_w2, n2_b2, scale2);   // zeroes g_sums

    // mlp1 + gelu: (768,192)@(192,4096) -> (768,4096)
    gemm_kernel<192, false, 1, true, false, false><<<dim3(32, 12), 256>>>(
        mlp_w1, x2, mlp_b1, nullptr, mb, 768, NPOS);

    // mlp2 + residual -> final output (C,N) == (1,192,16,16,16)
    gemm_kernel<768, false, 2, false, false, false><<<dim3(32, 3), 256>>>(
        mlp_w2, mb, mlp_b2, x2, out, 192, NPOS);
}

// round 6
// speedup vs baseline: 1.3321x; 1.0928x over previous
#include <cuda_runtime.h>
#include <cuda_fp16.h>
#include <cuda_bf16.h>
#include <math.h>

#define NPOS 4096
#define FULLM 0xffffffffu

// ---------------- scratch (static device globals; no allocation) -------------
__device__ float g_qkv[NPOS * 576];   // (pos, 576) pos-major
__device__ float g_o  [NPOS * 192];   // (pos, 192) pos-major
__device__ float g_x2 [192 * NPOS];   // (C, pos)  channel-major
__device__ float g_m  [768 * NPOS];   // (768, pos)
__device__ float g_sums[2 * 192];     // per-channel sum / sumsq (zero-init)
__device__ float g_mult[192];         // scale*gamma/rms
__device__ float g_h[384];            // norm-MLP hidden

// ---------------- bf16 helpers ------------------------------------------------
__device__ __forceinline__ void split_pack(float x, float y, unsigned& big, unsigned& small) {
    __nv_bfloat16 bx = __float2bfloat16_rn(x);
    __nv_bfloat16 by = __float2bfloat16_rn(y);
    __nv_bfloat16 sx = __float2bfloat16_rn(x - __bfloat162float(bx));
    __nv_bfloat16 sy = __float2bfloat16_rn(y - __bfloat162float(by));
    big   = ((unsigned)__bfloat16_as_ushort(by) << 16) | __bfloat16_as_ushort(bx);
    small = ((unsigned)__bfloat16_as_ushort(sy) << 16) | __bfloat16_as_ushort(sx);
}
__device__ __forceinline__ void mma_bf16(float* d, const unsigned* a, const unsigned* b) {
    asm volatile(
        "mma.sync.aligned.m16n8k16.row.col.f32.bf16.bf16.f32 "
        "{%0,%1,%2,%3},{%4,%5,%6,%7},{%8,%9},{%0,%1,%2,%3};"
        : "+f"(d[0]), "+f"(d[1]), "+f"(d[2]), "+f"(d[3])
        : "r"(a[0]), "r"(a[1]), "r"(a[2]), "r"(a[3]), "r"(b[0]), "r"(b[1]));
}

// ---------------- per-channel sum & sumsq over 4096 spatial elems ------------
__global__ void colstats_kernel(const float* __restrict__ x) {
    int c = blockIdx.x;
    const float* p = x + c * NPOS;
    float s = 0.f, s2 = 0.f;
    for (int i = threadIdx.x; i < NPOS; i += 256) {
        float v = p[i];
        s += v;
        s2 = fmaf(v, v, s2);
    }
    __shared__ float sh0[256], sh1[256];
    sh0[threadIdx.x] = s; sh1[threadIdx.x] = s2;
    __syncthreads();
    for (int o = 128; o > 0; o >>= 1) {
        if (threadIdx.x < o) {
            sh0[threadIdx.x] += sh0[threadIdx.x + o];
            sh1[threadIdx.x] += sh1[threadIdx.x + o];
        }
        __syncthreads();
    }
    if (threadIdx.x == 0) {
        g_sums[c]       = sh0[0];
        g_sums[192 + c] = sh1[0];
    }
}

// ---------------- norm-MLP layer 1 --------------------------------------------
__global__ void gamma1_kernel(const float* __restrict__ w1, const float* __restrict__ b1) {
    const int warp = threadIdx.x >> 5, lane = threadIdx.x & 31;
    const int ob = blockIdx.x * 16 + warp * 4;
    float a0 = 0.f, a1 = 0.f, a2 = 0.f, a3 = 0.f;
    #pragma unroll
    for (int j = 0; j < 6; j++) {
        float sv = g_sums[lane + j * 32] * (1.0f / 4096.0f);
        a0 = fmaf(sv, w1[(ob + 0) * 192 + lane + j * 32], a0);
        a1 = fmaf(sv, w1[(ob + 1) * 192 + lane + j * 32], a1);
        a2 = fmaf(sv, w1[(ob + 2) * 192 + lane + j * 32], a2);
        a3 = fmaf(sv, w1[(ob + 3) * 192 + lane + j * 32], a3);
    }
    #pragma unroll
    for (int off = 16; off; off >>= 1) {
        a0 += __shfl_xor_sync(FULLM, a0, off);
        a1 += __shfl_xor_sync(FULLM, a1, off);
        a2 += __shfl_xor_sync(FULLM, a2, off);
        a3 += __shfl_xor_sync(FULLM, a3, off);
    }
    if (lane == 0) {
        g_h[ob + 0] = fmaxf(a0 + b1[ob + 0], 0.f);
        g_h[ob + 1] = fmaxf(a1 + b1[ob + 1], 0.f);
        g_h[ob + 2] = fmaxf(a2 + b1[ob + 2], 0.f);
        g_h[ob + 3] = fmaxf(a3 + b1[ob + 3], 0.f);
    }
}

// ---------------- norm-MLP layer 2 -> g_mult; zeroes g_sums -------------------
__global__ void gamma2_kernel(const float* __restrict__ w2, const float* __restrict__ b2,
                              const float* __restrict__ scale) {
    const int warp = threadIdx.x >> 5, lane = threadIdx.x & 31;
    const int ob = blockIdx.x * 16 + warp * 4;
    float a0 = 0.f, a1 = 0.f, a2 = 0.f, a3 = 0.f;
    #pragma unroll
    for (int j = 0; j < 12; j++) {
        float hv = g_h[lane + j * 32];
        a0 = fmaf(hv, w2[(ob + 0) * 384 + lane + j * 32], a0);
        a1 = fmaf(hv, w2[(ob + 1) * 384 + lane + j * 32], a1);
        a2 = fmaf(hv, w2[(ob + 2) * 384 + lane + j * 32], a2);
        a3 = fmaf(hv, w2[(ob + 3) * 384 + lane + j * 32], a3);
    }
    #pragma unroll
    for (int off = 16; off; off >>= 1) {
        a0 += __shfl_xor_sync(FULLM, a0, off);
        a1 += __shfl_xor_sync(FULLM, a1, off);
        a2 += __shfl_xor_sync(FULLM, a2, off);
        a3 += __shfl_xor_sync(FULLM, a3, off);
    }
    if (lane == 0) {
        #pragma unroll
        for (int u = 0; u < 4; u++) {
            float a = (u == 0 ? a0 : u == 1 ? a1 : u == 2 ? a2 : a3) + b2[ob + u];
            float gamma = 1.f / (1.f + expf(-a));
            float rms = sqrtf(g_sums[192 + ob + u] * (1.0f / 4096.0f) + 1e-6f);
            g_mult[ob + u] = scale[ob + u] * gamma / rms;
            g_sums[ob + u] = 0.f;
            g_sums[192 + ob + u] = 0.f;
        }
    }
}

// ---------------- GEMM v5 (bf16x3 split, mma.m16n8k16) ------------------------
// out = epi(W(Co,Ci) @ X(Ci,N) + bias). Block 64(m) x 128(n), 256 thr = 8 warps
// in 2(m)x4(n); warp tile 32x32. K-tile 16, reg-prefetch pipeline.
// Smem: packed bf16x2 words, [row][k-pair] with stride 12 (conflict-free frags).
template <int CI, bool XN, int EPI, bool WS, bool STATS, bool OUTNCO>
__global__ void __launch_bounds__(256)
gemm_kernel(const float* __restrict__ W, const float* __restrict__ X,
            const float* __restrict__ bias, const float* __restrict__ res,
            float* __restrict__ out, int Co, int N) {
    __shared__ unsigned sAb[64 * 12], sAs[64 * 12];     // [m][k2]
    __shared__ unsigned sBb[128 * 12], sBs[128 * 12];   // [n][k2]
    const int NK = CI / 16;

    const int bn = blockIdx.x * 128;
    const int bm = blockIdx.y * 64;
    const int tid = threadIdx.x;
    const int warp = tid >> 5, lane = tid & 31;
    const int gid = lane >> 2, tig = lane & 3;
    const int wmb = (warp >> 2) * 32;
    const int wnb = (warp & 3) * 32;

    // staging roles: k-pair + row
    const int k2 = tid & 7;      // k-pair index 0..7
    const int rr = tid >> 3;     // 0..31

    float2 regA[2];
    float2 regB[4];

    float d[2][4][4];
    #pragma unroll
    for (int mt = 0; mt < 2; mt++)
        #pragma unroll
        for (int j = 0; j < 4; j++)
            #pragma unroll
            for (int e = 0; e < 4; e++) d[mt][j][e] = 0.f;

    auto loadTile = [&](int kk) {
        float gm0 = WS ? g_mult[kk + 2 * k2]     : 1.f;
        float gm1 = WS ? g_mult[kk + 2 * k2 + 1] : 1.f;
        #pragma unroll
        for (int r = 0; r < 2; r++) {
            float2 v = *(const float2*)&W[(size_t)(bm + rr + r * 32) * CI + kk + 2 * k2];
            regA[r] = make_float2(v.x * gm0, v.y * gm1);
        }
        if (XN) {
            #pragma unroll
            for (int r = 0; r < 4; r++)
                regB[r] = *(const float2*)&X[(size_t)(bn + rr + r * 32) * CI + kk + 2 * k2];
        } else {
            #pragma unroll
            for (int r = 0; r < 4; r++) {
                regB[r].x = X[(size_t)(kk + 2 * k2)     * N + bn + rr + r * 32];
                regB[r].y = X[(size_t)(kk + 2 * k2 + 1) * N + bn + rr + r * 32];
            }
        }
    };
    auto storeTile = [&]() {
        #pragma unroll
        for (int r = 0; r < 2; r++) {
            unsigned b, s;
            split_pack(regA[r].x, regA[r].y, b, s);
            sAb[(rr + r * 32) * 12 + k2] = b;
            sAs[(rr + r * 32) * 12 + k2] = s;
        }
        #pragma unroll
        for (int r = 0; r < 4; r++) {
            unsigned b, s;
            split_pack(regB[r].x, regB[r].y, b, s);
            sBb[(rr + r * 32) * 12 + k2] = b;
            sBs[(rr + r * 32) * 12 + k2] = s;
        }
    };

    loadTile(0);
    storeTile();
    __syncthreads();

    #pragma unroll 1
    for (int t = 0; t < NK; t++) {
        if (t + 1 < NK) loadTile((t + 1) * 16);

        unsigned Ab[2][4], As[2][4];
        #pragma unroll
        for (int mt = 0; mt < 2; mt++) {
            int m0 = wmb + 16 * mt + gid;
            Ab[mt][0] = sAb[m0 * 12 + tig];
            Ab[mt][1] = sAb[(m0 + 8) * 12 + tig];
            Ab[mt][2] = sAb[m0 * 12 + tig + 4];
            Ab[mt][3] = sAb[(m0 + 8) * 12 + tig + 4];
            As[mt][0] = sAs[m0 * 12 + tig];
            As[mt][1] = sAs[(m0 + 8) * 12 + tig];
            As[mt][2] = sAs[m0 * 12 + tig + 4];
            As[mt][3] = sAs[(m0 + 8) * 12 + tig + 4];
        }
        #pragma unroll
        for (int j = 0; j < 4; j++) {
            int n0 = wnb + 8 * j + gid;
            unsigned Bb[2] = { sBb[n0 * 12 + tig], sBb[n0 * 12 + tig + 4] };
            unsigned Bs[2] = { sBs[n0 * 12 + tig], sBs[n0 * 12 + tig + 4] };
            #pragma unroll
            for (int mt = 0; mt < 2; mt++) {
                mma_bf16(d[mt][j], Ab[mt], Bb);
                mma_bf16(d[mt][j], As[mt], Bb);
                mma_bf16(d[mt][j], Ab[mt], Bs);
            }
        }
        __syncthreads();
        if (t + 1 < NK) {
            storeTile();
            __syncthreads();
        }
    }

    // ---- epilogue ----
    const int gn0 = bn + wnb + 2 * tig;
    #pragma unroll
    for (int mt = 0; mt < 2; mt++) {
        #pragma unroll
        for (int half = 0; half < 2; half++) {
            int m = bm + wmb + 16 * mt + gid + 8 * half;
            float bv = bias[m];
            float v[8];
            #pragma unroll
            for (int j = 0; j < 4; j++) {
                v[2 * j]     = d[mt][j][2 * half]     + bv;
                v[2 * j + 1] = d[mt][j][2 * half + 1] + bv;
            }
            if (EPI == 1) {
                #pragma unroll
                for (int e = 0; e < 8; e++) {
                    float u = v[e];
                    v[e] = u * 0.5f * (1.f + erff(u * 0.70710678118654752f));
                }
            }
            if (EPI == 2) {
                #pragma unroll
                for (int j = 0; j < 4; j++) {
                    float2 r2 = *(const float2*)&res[(size_t)m * N + gn0 + 8 * j];
                    v[2 * j] += r2.x; v[2 * j + 1] += r2.y;
                }
            }
            if (STATS) {
                float ls = 0.f, ls2 = 0.f;
                #pragma unroll
                for (int e = 0; e < 8; e++) { ls += v[e]; ls2 = fmaf(v[e], v[e], ls2); }
                ls  += __shfl_xor_sync(FULLM, ls, 1);  ls  += __shfl_xor_sync(FULLM, ls, 2);
                ls2 += __shfl_xor_sync(FULLM, ls2, 1); ls2 += __shfl_xor_sync(FULLM, ls2, 2);
                if (tig == 0) {
                    atomicAdd(&g_sums[m], ls);
                    atomicAdd(&g_sums[192 + m], ls2);
                }
            }
            if (!OUTNCO) {
                #pragma unroll
                for (int j = 0; j < 4; j++)
                    *(float2*)&out[(size_t)m * N + gn0 + 8 * j] = make_float2(v[2 * j], v[2 * j + 1]);
            } else {
                #pragma unroll
                for (int j = 0; j < 4; j++) {
                    out[(size_t)(gn0 + 8 * j)     * Co + m] = v[2 * j];
                    out[(size_t)(gn0 + 8 * j + 1) * Co + m] = v[2 * j + 1];
                }
            }
        }
    }
}

// ---------------- 3D neighborhood attention (tiled, fp16 K/V in smem) ---------
__global__ void __launch_bounds__(256) attn_kernel(const float* __restrict__ qkv,
                                                   float* __restrict__ o) {
    extern __shared__ __align__(16) half2 sKV[];   // sK[8192] then sV[8192]
    half2* sK = sKV;
    half2* sV = sKV + 8192;

    const int tile = blockIdx.x, head = blockIdx.y;
    const int Td = ((tile >> 4) & 3) * 4, Th = ((tile >> 2) & 3) * 4, Tw = (tile & 3) * 4;
    const int Bd = min(max(Td - 2, 0), 8);
    const int Bh = min(max(Th - 2, 0), 8);
    const int Bw = min(max(Tw - 2, 0), 8);

    const int tid = threadIdx.x;

    #pragma unroll
    for (int it = 0; it < 16; it++) {
        int i = tid + it * 256;
        int row = i >> 3, g = i & 7;
        int rd = row >> 6, rh = (row >> 3) & 7, rw = row & 7;
        int gpos = ((Bd + rd) << 8) + ((Bh + rh) << 4) + (Bw + rw);
        const float* base = qkv + (size_t)gpos * 576 + head * 32 + g * 4;
        float4 kv = *(const float4*)(base + 192);
        float4 vv = *(const float4*)(base + 384);
        sK[row * 16 + g * 2]     = __floats2half2_rn(kv.x, kv.y);
        sK[row * 16 + g * 2 + 1] = __floats2half2_rn(kv.z, kv.w);
        sV[row * 16 + g * 2]     = __floats2half2_rn(vv.x, vv.y);
        sV[row * 16 + g * 2 + 1] = __floats2half2_rn(vv.z, vv.w);
    }

    const int quarter = tid & 3, vox = tid >> 2;
    const int aw = vox & 3, ah = (vox >> 2) & 3, ad = vox >> 4;
    const int vd = Td + ad, vh = Th + ah, vw = Tw + aw;
    const int gv = (vd << 8) + (vh << 4) + vw;
    const int ld = min(max(vd - 2, 0), 11) - Bd;
    const int lh = min(max(vh - 2, 0), 11) - Bh;
    const int lw = min(max(vw - 2, 0), 11) - Bw;
    const int rbase = ld * 64 + lh * 8 + lw;
    const int lane = tid & 31;

    float q[8];
    {
        const float* qp = qkv + (size_t)gv * 576 + head * 32 + quarter * 8;
        #pragma unroll
        for (int c = 0; c < 8; c++) q[c] = qp[c] * 0.17677669529663687f;
    }
    __syncthreads();

    float sc[32];
    #pragma unroll
    for (int i = 0; i < 32; i++) sc[i] = -1e30f;

    #pragma unroll
    for (int j = 0; j < 125; j++) {
        const int a = j / 25, b = (j / 5) % 5, c5 = j % 5;
        int row = rbase + a * 64 + b * 8 + c5;
        uint4 kk = *(const uint4*)(sK + row * 16 + quarter * 4);
        float2 f0 = __half22float2(*reinterpret_cast<half2*>(&kk.x));
        float2 f1 = __half22float2(*reinterpret_cast<half2*>(&kk.y));
        float2 f2 = __half22float2(*reinterpret_cast<half2*>(&kk.z));
        float2 f3 = __half22float2(*reinterpret_cast<half2*>(&kk.w));
        float p = q[0] * f0.x;
        p = fmaf(q[1], f0.y, p); p = fmaf(q[2], f1.x, p); p = fmaf(q[3], f1.y, p);
        p = fmaf(q[4], f2.x, p); p = fmaf(q[5], f2.y, p);
        p = fmaf(q[6], f3.x, p); p = fmaf(q[7], f3.y, p);
        p += __shfl_xor_sync(FULLM, p, 1);
        p += __shfl_xor_sync(FULLM, p, 2);
        if ((j & 3) == quarter) sc[j >> 2] = p;
    }

    float mx = -1e30f;
    #pragma unroll
    for (int i = 0; i < 32; i++) mx = fmaxf(mx, sc[i]);
    mx = fmaxf(mx, __shfl_xor_sync(FULLM, mx, 1));
    mx = fmaxf(mx, __shfl_xor_sync(FULLM, mx, 2));
    float tot = 0.f;
    #pragma unroll
    for (int i = 0; i < 32; i++) { sc[i] = __expf(sc[i] - mx); tot += sc[i]; }
    tot += __shfl_xor_sync(FULLM, tot, 1);
    tot += __shfl_xor_sync(FULLM, tot, 2);
    float inv = 1.f / tot;

    float o8[8] = {0.f, 0.f, 0.f, 0.f, 0.f, 0.f, 0.f, 0.f};
    #pragma unroll
    for (int j = 0; j < 125; j++) {
        const int a = j / 25, b = (j / 5) % 5, c5 = j % 5;
        float p = __shfl_sync(FULLM, sc[j >> 2], (lane & ~3) | (j & 3));
        int row = rbase + a * 64 + b * 8 + c5;
        uint4 vvp = *(const uint4*)(sV + row * 16 + quarter * 4);
        float2 f0 = __half22float2(*reinterpret_cast<half2*>(&vvp.x));
        float2 f1 = __half22float2(*reinterpret_cast<half2*>(&vvp.y));
        float2 f2 = __half22float2(*reinterpret_cast<half2*>(&vvp.z));
        float2 f3 = __half22float2(*reinterpret_cast<half2*>(&vvp.w));
        o8[0] = fmaf(p, f0.x, o8[0]); o8[1] = fmaf(p, f0.y, o8[1]);
        o8[2] = fmaf(p, f1.x, o8[2]); o8[3] = fmaf(p, f1.y, o8[3]);
        o8[4] = fmaf(p, f2.x, o8[4]); o8[5] = fmaf(p, f2.y, o8[5]);
        o8[6] = fmaf(p, f3.x, o8[6]); o8[7] = fmaf(p, f3.y, o8[7]);
    }
    float* op = o + (size_t)gv * 192 + head * 32 + quarter * 8;
    #pragma unroll
    for (int c = 0; c < 8; c++) op[c] = o8[c] * inv;
}

// ---------------- orchestration ----------------------------------------------
extern "C" void kernel_launch(void* const* d_in, const int* in_sizes, int n_in,
                              void* d_out, int out_size) {
    const float* x      = (const float*)d_in[0];
    const float* scale1 = (const float*)d_in[1];
    const float* n1_w1  = (const float*)d_in[2];
    const float* n1_b1  = (const float*)d_in[3];
    const float* n1_w2  = (const float*)d_in[4];
    const float* n1_b2  = (const float*)d_in[5];
    const float* qkv_w  = (const float*)d_in[6];
    const float* qkv_b  = (const float*)d_in[7];
    const float* proj_w = (const float*)d_in[8];
    const float* proj_b = (const float*)d_in[9];
    const float* scale2 = (const float*)d_in[10];
    const float* n2_w1  = (const float*)d_in[11];
    const float* n2_b1  = (const float*)d_in[12];
    const float* n2_w2  = (const float*)d_in[13];
    const float* n2_b2  = (const float*)d_in[14];
    const float* mlp_w1 = (const float*)d_in[15];
    const float* mlp_b1 = (const float*)d_in[16];
    const float* mlp_w2 = (const float*)d_in[17];
    const float* mlp_b2 = (const float*)d_in[18];
    float* out = (float*)d_out;

    float *qkv, *ob, *x2, *mb;
    cudaGetSymbolAddress((void**)&qkv, g_qkv);
    cudaGetSymbolAddress((void**)&ob,  g_o);
    cudaGetSymbolAddress((void**)&x2,  g_x2);
    cudaGetSymbolAddress((void**)&mb,  g_m);

    cudaFuncSetAttribute(attn_kernel, cudaFuncAttributeMaxDynamicSharedMemorySize, 65536);

    // ---- stage A ----
    colstats_kernel<<<192, 256>>>(x);
    gamma1_kernel<<<24, 128>>>(n1_w1, n1_b1);
    gamma2_kernel<<<12, 128>>>(n1_w2, n1_b2, scale1);   // zeroes g_sums

    // qkv: (576,192)@(192,4096) -> (4096,576) pos-major
    gemm_kernel<192, false, 0, true, false, true><<<dim3(32, 9), 256>>>(
        qkv_w, x, qkv_b, nullptr, qkv, 576, NPOS);

    // attention -> O (4096,192) pos-major
    attn_kernel<<<dim3(64, 6), 256, 65536>>>(qkv, ob);

    // proj + residual + fused stage-B colstats: x2 (C,N)
    gemm_kernel<192, true, 2, false, true, false><<<dim3(32, 3), 256>>>(
        proj_w, ob, proj_b, x, x2, 192, NPOS);

    // ---- stage B ----
    gamma1_kernel<<<24, 128>>>(n2_w1, n2_b1);
    gamma2_kernel<<<12, 128>>>(n2_w2, n2_b2, scale2);   // zeroes g_sums

    // mlp1 + gelu: (768,192)@(192,4096) -> (768,4096)
    gemm_kernel<192, false, 1, true, false, false><<<dim3(32, 12), 256>>>(
        mlp_w1, x2, mlp_b1, nullptr, mb, 768, NPOS);

    // mlp2 + residual -> final output (C,N) == (1,192,16,16,16)
    gemm_kernel<768, false, 2, false, false, false><<<dim3(32, 3), 256>>>(
        mlp_w2, mb, mlp_b2, x2, out, 192, NPOS);
}

// round 7
// speedup vs baseline: 1.3674x; 1.0265x over previous
#include <cuda_runtime.h>
#include <cuda_fp16.h>
#include <cuda_bf16.h>
#include <math.h>

#define NPOS 4096
#define FULLM 0xffffffffu

// ---------------- scratch (static device globals; no allocation) -------------
__device__ float g_qkv[NPOS * 576];   // (pos, 576) pos-major
__device__ float g_o  [NPOS * 192];   // (pos, 192) pos-major
__device__ float g_x2 [192 * NPOS];   // (C, pos)  channel-major
__device__ float g_m  [768 * NPOS];   // (768, pos)
__device__ float g_sums[2 * 192];     // per-channel sum / sumsq (zero-init)
__device__ float g_mult[192];         // scale*gamma/rms
__device__ float g_h[384];            // norm-MLP hidden

// ---------------- bf16 helpers ------------------------------------------------
__device__ __forceinline__ void split_pack(float x, float y, unsigned& big, unsigned& small) {
    __nv_bfloat16 bx = __float2bfloat16_rn(x);
    __nv_bfloat16 by = __float2bfloat16_rn(y);
    __nv_bfloat16 sx = __float2bfloat16_rn(x - __bfloat162float(bx));
    __nv_bfloat16 sy = __float2bfloat16_rn(y - __bfloat162float(by));
    big   = ((unsigned)__bfloat16_as_ushort(by) << 16) | __bfloat16_as_ushort(bx);
    small = ((unsigned)__bfloat16_as_ushort(sy) << 16) | __bfloat16_as_ushort(sx);
}
__device__ __forceinline__ void mma_bf16(float* d, const unsigned* a, const unsigned* b) {
    asm volatile(
        "mma.sync.aligned.m16n8k16.row.col.f32.bf16.bf16.f32 "
        "{%0,%1,%2,%3},{%4,%5,%6,%7},{%8,%9},{%0,%1,%2,%3};"
        : "+f"(d[0]), "+f"(d[1]), "+f"(d[2]), "+f"(d[3])
        : "r"(a[0]), "r"(a[1]), "r"(a[2]), "r"(a[3]), "r"(b[0]), "r"(b[1]));
}

// ---------------- per-channel sum & sumsq over 4096 spatial elems ------------
__global__ void colstats_kernel(const float* __restrict__ x) {
    int c = blockIdx.x;
    const float* p = x + c * NPOS;
    float s = 0.f, s2 = 0.f;
    for (int i = threadIdx.x; i < NPOS; i += 256) {
        float v = p[i];
        s += v;
        s2 = fmaf(v, v, s2);
    }
    __shared__ float sh0[256], sh1[256];
    sh0[threadIdx.x] = s; sh1[threadIdx.x] = s2;
    __syncthreads();
    for (int o = 128; o > 0; o >>= 1) {
        if (threadIdx.x < o) {
            sh0[threadIdx.x] += sh0[threadIdx.x + o];
            sh1[threadIdx.x] += sh1[threadIdx.x + o];
        }
        __syncthreads();
    }
    if (threadIdx.x == 0) {
        g_sums[c]       = sh0[0];
        g_sums[192 + c] = sh1[0];
    }
}

// ---------------- norm-MLP layer 1 --------------------------------------------
__global__ void gamma1_kernel(const float* __restrict__ w1, const float* __restrict__ b1) {
    const int warp = threadIdx.x >> 5, lane = threadIdx.x & 31;
    const int ob = blockIdx.x * 16 + warp * 4;
    float a0 = 0.f, a1 = 0.f, a2 = 0.f, a3 = 0.f;
    #pragma unroll
    for (int j = 0; j < 6; j++) {
        float sv = g_sums[lane + j * 32] * (1.0f / 4096.0f);
        a0 = fmaf(sv, w1[(ob + 0) * 192 + lane + j * 32], a0);
        a1 = fmaf(sv, w1[(ob + 1) * 192 + lane + j * 32], a1);
        a2 = fmaf(sv, w1[(ob + 2) * 192 + lane + j * 32], a2);
        a3 = fmaf(sv, w1[(ob + 3) * 192 + lane + j * 32], a3);
    }
    #pragma unroll
    for (int off = 16; off; off >>= 1) {
        a0 += __shfl_xor_sync(FULLM, a0, off);
        a1 += __shfl_xor_sync(FULLM, a1, off);
        a2 += __shfl_xor_sync(FULLM, a2, off);
        a3 += __shfl_xor_sync(FULLM, a3, off);
    }
    if (lane == 0) {
        g_h[ob + 0] = fmaxf(a0 + b1[ob + 0], 0.f);
        g_h[ob + 1] = fmaxf(a1 + b1[ob + 1], 0.f);
        g_h[ob + 2] = fmaxf(a2 + b1[ob + 2], 0.f);
        g_h[ob + 3] = fmaxf(a3 + b1[ob + 3], 0.f);
    }
}

// ---------------- norm-MLP layer 2 -> g_mult; zeroes g_sums -------------------
__global__ void gamma2_kernel(const float* __restrict__ w2, const float* __restrict__ b2,
                              const float* __restrict__ scale) {
    const int warp = threadIdx.x >> 5, lane = threadIdx.x & 31;
    const int ob = blockIdx.x * 16 + warp * 4;
    float a0 = 0.f, a1 = 0.f, a2 = 0.f, a3 = 0.f;
    #pragma unroll
    for (int j = 0; j < 12; j++) {
        float hv = g_h[lane + j * 32];
        a0 = fmaf(hv, w2[(ob + 0) * 384 + lane + j * 32], a0);
        a1 = fmaf(hv, w2[(ob + 1) * 384 + lane + j * 32], a1);
        a2 = fmaf(hv, w2[(ob + 2) * 384 + lane + j * 32], a2);
        a3 = fmaf(hv, w2[(ob + 3) * 384 + lane + j * 32], a3);
    }
    #pragma unroll
    for (int off = 16; off; off >>= 1) {
        a0 += __shfl_xor_sync(FULLM, a0, off);
        a1 += __shfl_xor_sync(FULLM, a1, off);
        a2 += __shfl_xor_sync(FULLM, a2, off);
        a3 += __shfl_xor_sync(FULLM, a3, off);
    }
    if (lane == 0) {
        #pragma unroll
        for (int u = 0; u < 4; u++) {
            float a = (u == 0 ? a0 : u == 1 ? a1 : u == 2 ? a2 : a3) + b2[ob + u];
            float gamma = 1.f / (1.f + expf(-a));
            float rms = sqrtf(g_sums[192 + ob + u] * (1.0f / 4096.0f) + 1e-6f);
            g_mult[ob + u] = scale[ob + u] * gamma / rms;
            g_sums[ob + u] = 0.f;
            g_sums[192 + ob + u] = 0.f;
        }
    }
}

// ---------------- GEMM v6 (bf16x3, m16n8k16, 2-stage smem pipeline) -----------
// out = epi(W(Co,Ci) @ X(Ci,N) + bias).
// NT=128: block 64m x 128n, 256 thr (8 warps, 2x4).  NT=64: 64m x 64n, 128 thr
// (4 warps, 2x2) -- more blocks for small-Co GEMMs. One barrier per K-tile.
template <int CI, int NT, bool XN, int EPI, bool WS, bool STATS, bool OUTNCO>
__global__ void __launch_bounds__(NT * 2)
gemm_kernel(const float* __restrict__ W, const float* __restrict__ X,
            const float* __restrict__ bias, const float* __restrict__ res,
            float* __restrict__ out, int Co, int N) {
    __shared__ unsigned sAb[2][64 * 12], sAs[2][64 * 12];   // [stage][m][k2]
    __shared__ unsigned sBb[2][NT * 12], sBs[2][NT * 12];   // [stage][n][k2]
    const int NK = CI / 16;
    const int T = NT * 2;            // threads
    const int RSTRIDE = T / 8;       // staging row stride (32 or 16)
    const int AROWS = 64 / RSTRIDE;  // per-thread A rows (2 or 4)
    const int BROWS = NT / RSTRIDE;  // per-thread B rows (4)

    const int bn = blockIdx.x * NT;
    const int bm = blockIdx.y * 64;
    const int tid = threadIdx.x;
    const int warp = tid >> 5, lane = tid & 31;
    const int gid = lane >> 2, tig = lane & 3;
    const int wmb = (NT == 128) ? (warp >> 2) * 32 : (warp >> 1) * 32;
    const int wnb = (NT == 128) ? (warp & 3) * 32 : (warp & 1) * 32;

    const int k2 = tid & 7;
    const int rr = tid >> 3;

    float2 regA[AROWS];
    float2 regB[BROWS];

    float d[2][4][4];
    #pragma unroll
    for (int mt = 0; mt < 2; mt++)
        #pragma unroll
        for (int j = 0; j < 4; j++)
            #pragma unroll
            for (int e = 0; e < 4; e++) d[mt][j][e] = 0.f;

    auto loadTile = [&](int kk) {
        float gm0 = WS ? g_mult[kk + 2 * k2]     : 1.f;
        float gm1 = WS ? g_mult[kk + 2 * k2 + 1] : 1.f;
        #pragma unroll
        for (int r = 0; r < AROWS; r++) {
            float2 v = *(const float2*)&W[(size_t)(bm + rr + r * RSTRIDE) * CI + kk + 2 * k2];
            regA[r] = make_float2(v.x * gm0, v.y * gm1);
        }
        if (XN) {
            #pragma unroll
            for (int r = 0; r < BROWS; r++)
                regB[r] = *(const float2*)&X[(size_t)(bn + rr + r * RSTRIDE) * CI + kk + 2 * k2];
        } else {
            #pragma unroll
            for (int r = 0; r < BROWS; r++) {
                regB[r].x = X[(size_t)(kk + 2 * k2)     * N + bn + rr + r * RSTRIDE];
                regB[r].y = X[(size_t)(kk + 2 * k2 + 1) * N + bn + rr + r * RSTRIDE];
            }
        }
    };
    auto storeTile = [&](int st) {
        #pragma unroll
        for (int r = 0; r < AROWS; r++) {
            unsigned b, s;
            split_pack(regA[r].x, regA[r].y, b, s);
            sAb[st][(rr + r * RSTRIDE) * 12 + k2] = b;
            sAs[st][(rr + r * RSTRIDE) * 12 + k2] = s;
        }
        #pragma unroll
        for (int r = 0; r < BROWS; r++) {
            unsigned b, s;
            split_pack(regB[r].x, regB[r].y, b, s);
            sBb[st][(rr + r * RSTRIDE) * 12 + k2] = b;
            sBs[st][(rr + r * RSTRIDE) * 12 + k2] = s;
        }
    };

    loadTile(0);
    storeTile(0);
    __syncthreads();

    #pragma unroll 1
    for (int t = 0; t < NK; t++) {
        const int cur = t & 1;
        if (t + 1 < NK) loadTile((t + 1) * 16);

        unsigned Ab[2][4], As[2][4];
        #pragma unroll
        for (int mt = 0; mt < 2; mt++) {
            int m0 = wmb + 16 * mt + gid;
            Ab[mt][0] = sAb[cur][m0 * 12 + tig];
            Ab[mt][1] = sAb[cur][(m0 + 8) * 12 + tig];
            Ab[mt][2] = sAb[cur][m0 * 12 + tig + 4];
            Ab[mt][3] = sAb[cur][(m0 + 8) * 12 + tig + 4];
            As[mt][0] = sAs[cur][m0 * 12 + tig];
            As[mt][1] = sAs[cur][(m0 + 8) * 12 + tig];
            As[mt][2] = sAs[cur][m0 * 12 + tig + 4];
            As[mt][3] = sAs[cur][(m0 + 8) * 12 + tig + 4];
        }
        #pragma unroll
        for (int j = 0; j < 4; j++) {
            int n0 = wnb + 8 * j + gid;
            unsigned Bb[2] = { sBb[cur][n0 * 12 + tig], sBb[cur][n0 * 12 + tig + 4] };
            unsigned Bs[2] = { sBs[cur][n0 * 12 + tig], sBs[cur][n0 * 12 + tig + 4] };
            #pragma unroll
            for (int mt = 0; mt < 2; mt++) {
                mma_bf16(d[mt][j], Ab[mt], Bb);
                mma_bf16(d[mt][j], As[mt], Bb);
                mma_bf16(d[mt][j], Ab[mt], Bs);
            }
        }
        if (t + 1 < NK) storeTile(1 - cur);
        __syncthreads();
    }

    // ---- epilogue ----
    const int gn0 = bn + wnb + 2 * tig;
    #pragma unroll
    for (int mt = 0; mt < 2; mt++) {
        #pragma unroll
        for (int half = 0; half < 2; half++) {
            int m = bm + wmb + 16 * mt + gid + 8 * half;
            float bv = bias[m];
            float v[8];
            #pragma unroll
            for (int j = 0; j < 4; j++) {
                v[2 * j]     = d[mt][j][2 * half]     + bv;
                v[2 * j + 1] = d[mt][j][2 * half + 1] + bv;
            }
            if (EPI == 1) {
                #pragma unroll
                for (int e = 0; e < 8; e++) {
                    float u = v[e];
                    v[e] = u * 0.5f * (1.f + erff(u * 0.70710678118654752f));
                }
            }
            if (EPI == 2) {
                #pragma unroll
                for (int j = 0; j < 4; j++) {
                    float2 r2 = *(const float2*)&res[(size_t)m * N + gn0 + 8 * j];
                    v[2 * j] += r2.x; v[2 * j + 1] += r2.y;
                }
            }
            if (STATS) {
                float ls = 0.f, ls2 = 0.f;
                #pragma unroll
                for (int e = 0; e < 8; e++) { ls += v[e]; ls2 = fmaf(v[e], v[e], ls2); }
                ls  += __shfl_xor_sync(FULLM, ls, 1);  ls  += __shfl_xor_sync(FULLM, ls, 2);
                ls2 += __shfl_xor_sync(FULLM, ls2, 1); ls2 += __shfl_xor_sync(FULLM, ls2, 2);
                if (tig == 0) {
                    atomicAdd(&g_sums[m], ls);
                    atomicAdd(&g_sums[192 + m], ls2);
                }
            }
            if (!OUTNCO) {
                #pragma unroll
                for (int j = 0; j < 4; j++)
                    *(float2*)&out[(size_t)m * N + gn0 + 8 * j] = make_float2(v[2 * j], v[2 * j + 1]);
            } else {
                #pragma unroll
                for (int j = 0; j < 4; j++) {
                    out[(size_t)(gn0 + 8 * j)     * Co + m] = v[2 * j];
                    out[(size_t)(gn0 + 8 * j + 1) * Co + m] = v[2 * j + 1];
                }
            }
        }
    }
}

// ---------------- 3D neighborhood attention (tiled, fp16 K/V in smem) ---------
__global__ void __launch_bounds__(256) attn_kernel(const float* __restrict__ qkv,
                                                   float* __restrict__ o) {
    extern __shared__ __align__(16) half2 sKV[];   // sK[8192] then sV[8192]
    half2* sK = sKV;
    half2* sV = sKV + 8192;

    const int tile = blockIdx.x, head = blockIdx.y;
    const int Td = ((tile >> 4) & 3) * 4, Th = ((tile >> 2) & 3) * 4, Tw = (tile & 3) * 4;
    const int Bd = min(max(Td - 2, 0), 8);
    const int Bh = min(max(Th - 2, 0), 8);
    const int Bw = min(max(Tw - 2, 0), 8);

    const int tid = threadIdx.x;

    #pragma unroll
    for (int it = 0; it < 16; it++) {
        int i = tid + it * 256;
        int row = i >> 3, g = i & 7;
        int rd = row >> 6, rh = (row >> 3) & 7, rw = row & 7;
        int gpos = ((Bd + rd) << 8) + ((Bh + rh) << 4) + (Bw + rw);
        const float* base = qkv + (size_t)gpos * 576 + head * 32 + g * 4;
        float4 kv = *(const float4*)(base + 192);
        float4 vv = *(const float4*)(base + 384);
        sK[row * 16 + g * 2]     = __floats2half2_rn(kv.x, kv.y);
        sK[row * 16 + g * 2 + 1] = __floats2half2_rn(kv.z, kv.w);
        sV[row * 16 + g * 2]     = __floats2half2_rn(vv.x, vv.y);
        sV[row * 16 + g * 2 + 1] = __floats2half2_rn(vv.z, vv.w);
    }

    const int quarter = tid & 3, vox = tid >> 2;
    const int aw = vox & 3, ah = (vox >> 2) & 3, ad = vox >> 4;
    const int vd = Td + ad, vh = Th + ah, vw = Tw + aw;
    const int gv = (vd << 8) + (vh << 4) + vw;
    const int ld = min(max(vd - 2, 0), 11) - Bd;
    const int lh = min(max(vh - 2, 0), 11) - Bh;
    const int lw = min(max(vw - 2, 0), 11) - Bw;
    const int rbase = ld * 64 + lh * 8 + lw;
    const int lane = tid & 31;

    float q[8];
    {
        const float* qp = qkv + (size_t)gv * 576 + head * 32 + quarter * 8;
        #pragma unroll
        for (int c = 0; c < 8; c++) q[c] = qp[c] * 0.17677669529663687f;
    }
    __syncthreads();

    float sc[32];
    #pragma unroll
    for (int i = 0; i < 32; i++) sc[i] = -1e30f;

    #pragma unroll
    for (int j = 0; j < 125; j++) {
        const int a = j / 25, b = (j / 5) % 5, c5 = j % 5;
        int row = rbase + a * 64 + b * 8 + c5;
        uint4 kk = *(const uint4*)(sK + row * 16 + quarter * 4);
        float2 f0 = __half22float2(*reinterpret_cast<half2*>(&kk.x));
        float2 f1 = __half22float2(*reinterpret_cast<half2*>(&kk.y));
        float2 f2 = __half22float2(*reinterpret_cast<half2*>(&kk.z));
        float2 f3 = __half22float2(*reinterpret_cast<half2*>(&kk.w));
        float p = q[0] * f0.x;
        p = fmaf(q[1], f0.y, p); p = fmaf(q[2], f1.x, p); p = fmaf(q[3], f1.y, p);
        p = fmaf(q[4], f2.x, p); p = fmaf(q[5], f2.y, p);
        p = fmaf(q[6], f3.x, p); p = fmaf(q[7], f3.y, p);
        p += __shfl_xor_sync(FULLM, p, 1);
        p += __shfl_xor_sync(FULLM, p, 2);
        if ((j & 3) == quarter) sc[j >> 2] = p;
    }

    float mx = -1e30f;
    #pragma unroll
    for (int i = 0; i < 32; i++) mx = fmaxf(mx, sc[i]);
    mx = fmaxf(mx, __shfl_xor_sync(FULLM, mx, 1));
    mx = fmaxf(mx, __shfl_xor_sync(FULLM, mx, 2));
    float tot = 0.f;
    #pragma unroll
    for (int i = 0; i < 32; i++) { sc[i] = __expf(sc[i] - mx); tot += sc[i]; }
    tot += __shfl_xor_sync(FULLM, tot, 1);
    tot += __shfl_xor_sync(FULLM, tot, 2);
    float inv = 1.f / tot;

    float o8[8] = {0.f, 0.f, 0.f, 0.f, 0.f, 0.f, 0.f, 0.f};
    #pragma unroll
    for (int j = 0; j < 125; j++) {
        const int a = j / 25, b = (j / 5) % 5, c5 = j % 5;
        float p = __shfl_sync(FULLM, sc[j >> 2], (lane & ~3) | (j & 3));
        int row = rbase + a * 64 + b * 8 + c5;
        uint4 vvp = *(const uint4*)(sV + row * 16 + quarter * 4);
        float2 f0 = __half22float2(*reinterpret_cast<half2*>(&vvp.x));
        float2 f1 = __half22float2(*reinterpret_cast<half2*>(&vvp.y));
        float2 f2 = __half22float2(*reinterpret_cast<half2*>(&vvp.z));
        float2 f3 = __half22float2(*reinterpret_cast<half2*>(&vvp.w));
        o8[0] = fmaf(p, f0.x, o8[0]); o8[1] = fmaf(p, f0.y, o8[1]);
        o8[2] = fmaf(p, f1.x, o8[2]); o8[3] = fmaf(p, f1.y, o8[3]);
        o8[4] = fmaf(p, f2.x, o8[4]); o8[5] = fmaf(p, f2.y, o8[5]);
        o8[6] = fmaf(p, f3.x, o8[6]); o8[7] = fmaf(p, f3.y, o8[7]);
    }
    float* op = o + (size_t)gv * 192 + head * 32 + quarter * 8;
    #pragma unroll
    for (int c = 0; c < 8; c++) op[c] = o8[c] * inv;
}

// ---------------- orchestration ----------------------------------------------
extern "C" void kernel_launch(void* const* d_in, const int* in_sizes, int n_in,
                              void* d_out, int out_size) {
    const float* x      = (const float*)d_in[0];
    const float* scale1 = (const float*)d_in[1];
    const float* n1_w1  = (const float*)d_in[2];
    const float* n1_b1  = (const float*)d_in[3];
    const float* n1_w2  = (const float*)d_in[4];
    const float* n1_b2  = (const float*)d_in[5];
    const float* qkv_w  = (const float*)d_in[6];
    const float* qkv_b  = (const float*)d_in[7];
    const float* proj_w = (const float*)d_in[8];
    const float* proj_b = (const float*)d_in[9];
    const float* scale2 = (const float*)d_in[10];
    const float* n2_w1  = (const float*)d_in[11];
    const float* n2_b1  = (const float*)d_in[12];
    const float* n2_w2  = (const float*)d_in[13];
    const float* n2_b2  = (const float*)d_in[14];
    const float* mlp_w1 = (const float*)d_in[15];
    const float* mlp_b1 = (const float*)d_in[16];
    const float* mlp_w2 = (const float*)d_in[17];
    const float* mlp_b2 = (const float*)d_in[18];
    float* out = (float*)d_out;

    float *qkv, *ob, *x2, *mb;
    cudaGetSymbolAddress((void**)&qkv, g_qkv);
    cudaGetSymbolAddress((void**)&ob,  g_o);
    cudaGetSymbolAddress((void**)&x2,  g_x2);
    cudaGetSymbolAddress((void**)&mb,  g_m);

    cudaFuncSetAttribute(attn_kernel, cudaFuncAttributeMaxDynamicSharedMemorySize, 65536);

    // ---- stage A ----
    colstats_kernel<<<192, 256>>>(x);
    gamma1_kernel<<<24, 128>>>(n1_w1, n1_b1);
    gamma2_kernel<<<12, 128>>>(n1_w2, n1_b2, scale1);   // zeroes g_sums

    // qkv: (576,192)@(192,4096) -> (4096,576) pos-major
    gemm_kernel<192, 128, false, 0, true, false, true><<<dim3(32, 9), 256>>>(
        qkv_w, x, qkv_b, nullptr, qkv, 576, NPOS);

    // attention -> O (4096,192) pos-major
    attn_kernel<<<dim3(64, 6), 256, 65536>>>(qkv, ob);

    // proj + residual + fused stage-B colstats: x2 (C,N)
    gemm_kernel<192, 64, true, 2, false, true, false><<<dim3(64, 3), 128>>>(
        proj_w, ob, proj_b, x, x2, 192, NPOS);

    // ---- stage B ----
    gamma1_kernel<<<24, 128>>>(n2_w1, n2_b1);
    gamma2_kernel<<<12, 128>>>(n2_w2, n2_b2, scale2);   // zeroes g_sums

    // mlp1 + gelu: (768,192)@(192,4096) -> (768,4096)
    gemm_kernel<192, 128, false, 1, true, false, false><<<dim3(32, 12), 256>>>(
        mlp_w1, x2, mlp_b1, nullptr, mb, 768, NPOS);

    // mlp2 + residual -> final output (C,N) == (1,192,16,16,16)
    gemm_kernel<768, 64, false, 2, false, false, false><<<dim3(64, 3), 128>>>(
        mlp_w2, mb, mlp_b2, x2, out, 192, NPOS);
}

// round 8
// speedup vs baseline: 1.4445x; 1.0564x over previous
#include <cuda_runtime.h>
#include <cuda_fp16.h>
#include <cuda_bf16.h>
#include <math.h>

#define NPOS 4096
#define FULLM 0xffffffffu

// ---------------- scratch (static device globals; no allocation) -------------
__device__ float g_qkv[NPOS * 576];   // (pos, 576) pos-major
__device__ float g_o  [NPOS * 192];   // (pos, 192) pos-major
__device__ float g_x2 [192 * NPOS];   // (C, pos)  channel-major
__device__ float g_m  [768 * NPOS];   // (768, pos)
__device__ float g_sums[2 * 192];     // per-channel sum / sumsq (zero-init)
__device__ float g_mult[192];         // scale*gamma/rms
__device__ float g_h[384];            // norm-MLP hidden

// ---------------- bf16 helpers ------------------------------------------------
__device__ __forceinline__ void split_pack(float x, float y, unsigned& big, unsigned& small) {
    __nv_bfloat16 bx = __float2bfloat16_rn(x);
    __nv_bfloat16 by = __float2bfloat16_rn(y);
    __nv_bfloat16 sx = __float2bfloat16_rn(x - __bfloat162float(bx));
    __nv_bfloat16 sy = __float2bfloat16_rn(y - __bfloat162float(by));
    big   = ((unsigned)__bfloat16_as_ushort(by) << 16) | __bfloat16_as_ushort(bx);
    small = ((unsigned)__bfloat16_as_ushort(sy) << 16) | __bfloat16_as_ushort(sx);
}
__device__ __forceinline__ void mma_bf16(float* d, const unsigned* a, const unsigned* b) {
    asm volatile(
        "mma.sync.aligned.m16n8k16.row.col.f32.bf16.bf16.f32 "
        "{%0,%1,%2,%3},{%4,%5,%6,%7},{%8,%9},{%0,%1,%2,%3};"
        : "+f"(d[0]), "+f"(d[1]), "+f"(d[2]), "+f"(d[3])
        : "r"(a[0]), "r"(a[1]), "r"(a[2]), "r"(a[3]), "r"(b[0]), "r"(b[1]));
}

// ---------------- per-channel sum & sumsq over 4096 spatial elems ------------
__global__ void colstats_kernel(const float* __restrict__ x) {
    int c = blockIdx.x;
    const float* p = x + c * NPOS;
    float s = 0.f, s2 = 0.f;
    for (int i = threadIdx.x; i < NPOS; i += 256) {
        float v = p[i];
        s += v;
        s2 = fmaf(v, v, s2);
    }
    __shared__ float sh0[256], sh1[256];
    sh0[threadIdx.x] = s; sh1[threadIdx.x] = s2;
    __syncthreads();
    for (int o = 128; o > 0; o >>= 1) {
        if (threadIdx.x < o) {
            sh0[threadIdx.x] += sh0[threadIdx.x + o];
            sh1[threadIdx.x] += sh1[threadIdx.x + o];
        }
        __syncthreads();
    }
    if (threadIdx.x == 0) {
        g_sums[c]       = sh0[0];
        g_sums[192 + c] = sh1[0];
    }
}

// ---------------- norm-MLP layer 1 --------------------------------------------
__global__ void gamma1_kernel(const float* __restrict__ w1, const float* __restrict__ b1) {
    const int warp = threadIdx.x >> 5, lane = threadIdx.x & 31;
    const int ob = blockIdx.x * 16 + warp * 4;
    float a0 = 0.f, a1 = 0.f, a2 = 0.f, a3 = 0.f;
    #pragma unroll
    for (int j = 0; j < 6; j++) {
        float sv = g_sums[lane + j * 32] * (1.0f / 4096.0f);
        a0 = fmaf(sv, w1[(ob + 0) * 192 + lane + j * 32], a0);
        a1 = fmaf(sv, w1[(ob + 1) * 192 + lane + j * 32], a1);
        a2 = fmaf(sv, w1[(ob + 2) * 192 + lane + j * 32], a2);
        a3 = fmaf(sv, w1[(ob + 3) * 192 + lane + j * 32], a3);
    }
    #pragma unroll
    for (int off = 16; off; off >>= 1) {
        a0 += __shfl_xor_sync(FULLM, a0, off);
        a1 += __shfl_xor_sync(FULLM, a1, off);
        a2 += __shfl_xor_sync(FULLM, a2, off);
        a3 += __shfl_xor_sync(FULLM, a3, off);
    }
    if (lane == 0) {
        g_h[ob + 0] = fmaxf(a0 + b1[ob + 0], 0.f);
        g_h[ob + 1] = fmaxf(a1 + b1[ob + 1], 0.f);
        g_h[ob + 2] = fmaxf(a2 + b1[ob + 2], 0.f);
        g_h[ob + 3] = fmaxf(a3 + b1[ob + 3], 0.f);
    }
}

// ---------------- norm-MLP layer 2 -> g_mult; zeroes g_sums -------------------
__global__ void gamma2_kernel(const float* __restrict__ w2, const float* __restrict__ b2,
                              const float* __restrict__ scale) {
    const int warp = threadIdx.x >> 5, lane = threadIdx.x & 31;
    const int ob = blockIdx.x * 16 + warp * 4;
    float a0 = 0.f, a1 = 0.f, a2 = 0.f, a3 = 0.f;
    #pragma unroll
    for (int j = 0; j < 12; j++) {
        float hv = g_h[lane + j * 32];
        a0 = fmaf(hv, w2[(ob + 0) * 384 + lane + j * 32], a0);
        a1 = fmaf(hv, w2[(ob + 1) * 384 + lane + j * 32], a1);
        a2 = fmaf(hv, w2[(ob + 2) * 384 + lane + j * 32], a2);
        a3 = fmaf(hv, w2[(ob + 3) * 384 + lane + j * 32], a3);
    }
    #pragma unroll
    for (int off = 16; off; off >>= 1) {
        a0 += __shfl_xor_sync(FULLM, a0, off);
        a1 += __shfl_xor_sync(FULLM, a1, off);
        a2 += __shfl_xor_sync(FULLM, a2, off);
        a3 += __shfl_xor_sync(FULLM, a3, off);
    }
    if (lane == 0) {
        #pragma unroll
        for (int u = 0; u < 4; u++) {
            float a = (u == 0 ? a0 : u == 1 ? a1 : u == 2 ? a2 : a3) + b2[ob + u];
            float gamma = 1.f / (1.f + expf(-a));
            float rms = sqrtf(g_sums[192 + ob + u] * (1.0f / 4096.0f) + 1e-6f);
            g_mult[ob + u] = scale[ob + u] * gamma / rms;
            g_sums[ob + u] = 0.f;
            g_sums[192 + ob + u] = 0.f;
        }
    }
}

// ---------------- out init for split-K: out = res + bias ----------------------
__global__ void initout_kernel(const float* __restrict__ res, const float* __restrict__ bias,
                               float* __restrict__ out) {
    int i = blockIdx.x * 256 + threadIdx.x;       // over 196608 float4s
    float4 v = ((const float4*)res)[i];
    float b = bias[i >> 10];                      // 1024 float4s per row
    v.x += b; v.y += b; v.z += b; v.w += b;
    ((float4*)out)[i] = v;
}

// ---------------- GEMM v7 (bf16x3, m16n8k16, 64x64 blocks, split-K) -----------
// out = epi(W(Co,CIFULL) @ X + bias). Block 64m x 64n, 128 thr (4 warps, 2x2).
// blockIdx.z selects a CI-sized K-slice at kbase = z*CI (CIFULL = W leading dim).
// EPI: 0 none, 1 exact gelu, 2 +res, 3 atomicAdd into pre-initialized out.
template <int CI, int CIFULL, bool XN, int EPI, bool WS, bool STATS, bool OUTNCO>
__global__ void __launch_bounds__(128)
gemm_kernel(const float* __restrict__ W, const float* __restrict__ X,
            const float* __restrict__ bias, const float* __restrict__ res,
            float* __restrict__ out, int Co, int N) {
    __shared__ unsigned sAb[2][64 * 12], sAs[2][64 * 12];   // [stage][m][k2]
    __shared__ unsigned sBb[2][64 * 12], sBs[2][64 * 12];   // [stage][n][k2]
    const int NK = CI / 16;

    const int bn = blockIdx.x * 64;
    const int bm = blockIdx.y * 64;
    const int kbase = blockIdx.z * CI;
    const int tid = threadIdx.x;
    const int warp = tid >> 5, lane = tid & 31;
    const int gid = lane >> 2, tig = lane & 3;
    const int wmb = (warp >> 1) * 32;
    const int wnb = (warp & 1) * 32;

    const int k2 = tid & 7;      // k-pair 0..7
    const int rr = tid >> 3;     // 0..15
    float2 regA[4];
    float2 regB[4];

    float d[2][4][4];
    #pragma unroll
    for (int mt = 0; mt < 2; mt++)
        #pragma unroll
        for (int j = 0; j < 4; j++)
            #pragma unroll
            for (int e = 0; e < 4; e++) d[mt][j][e] = 0.f;

    auto loadTile = [&](int kk) {
        float gm0 = WS ? g_mult[kbase + kk + 2 * k2]     : 1.f;
        float gm1 = WS ? g_mult[kbase + kk + 2 * k2 + 1] : 1.f;
        #pragma unroll
        for (int r = 0; r < 4; r++) {
            float2 v = *(const float2*)&W[(size_t)(bm + rr + r * 16) * CIFULL + kbase + kk + 2 * k2];
            regA[r] = make_float2(v.x * gm0, v.y * gm1);
        }
        if (XN) {
            #pragma unroll
            for (int r = 0; r < 4; r++)
                regB[r] = *(const float2*)&X[(size_t)(bn + rr + r * 16) * CIFULL + kbase + kk + 2 * k2];
        } else {
            #pragma unroll
            for (int r = 0; r < 4; r++) {
                regB[r].x = X[(size_t)(kbase + kk + 2 * k2)     * N + bn + rr + r * 16];
                regB[r].y = X[(size_t)(kbase + kk + 2 * k2 + 1) * N + bn + rr + r * 16];
            }
        }
    };
    auto storeTile = [&](int st) {
        #pragma unroll
        for (int r = 0; r < 4; r++) {
            unsigned b, s;
            split_pack(regA[r].x, regA[r].y, b, s);
            sAb[st][(rr + r * 16) * 12 + k2] = b;
            sAs[st][(rr + r * 16) * 12 + k2] = s;
        }
        #pragma unroll
        for (int r = 0; r < 4; r++) {
            unsigned b, s;
            split_pack(regB[r].x, regB[r].y, b, s);
            sBb[st][(rr + r * 16) * 12 + k2] = b;
            sBs[st][(rr + r * 16) * 12 + k2] = s;
        }
    };

    loadTile(0);
    storeTile(0);
    __syncthreads();

    #pragma unroll 1
    for (int t = 0; t < NK; t++) {
        const int cur = t & 1;
        if (t + 1 < NK) loadTile((t + 1) * 16);

        unsigned Ab[2][4], As[2][4];
        #pragma unroll
        for (int mt = 0; mt < 2; mt++) {
            int m0 = wmb + 16 * mt + gid;
            Ab[mt][0] = sAb[cur][m0 * 12 + tig];
            Ab[mt][1] = sAb[cur][(m0 + 8) * 12 + tig];
            Ab[mt][2] = sAb[cur][m0 * 12 + tig + 4];
            Ab[mt][3] = sAb[cur][(m0 + 8) * 12 + tig + 4];
            As[mt][0] = sAs[cur][m0 * 12 + tig];
            As[mt][1] = sAs[cur][(m0 + 8) * 12 + tig];
            As[mt][2] = sAs[cur][m0 * 12 + tig + 4];
            As[mt][3] = sAs[cur][(m0 + 8) * 12 + tig + 4];
        }
        #pragma unroll
        for (int j = 0; j < 4; j++) {
            int n0 = wnb + 8 * j + gid;
            unsigned Bb[2] = { sBb[cur][n0 * 12 + tig], sBb[cur][n0 * 12 + tig + 4] };
            unsigned Bs[2] = { sBs[cur][n0 * 12 + tig], sBs[cur][n0 * 12 + tig + 4] };
            #pragma unroll
            for (int mt = 0; mt < 2; mt++) {
                mma_bf16(d[mt][j], Ab[mt], Bb);
                mma_bf16(d[mt][j], As[mt], Bb);
                mma_bf16(d[mt][j], Ab[mt], Bs);
            }
        }
        if (t + 1 < NK) storeTile(1 - cur);
        __syncthreads();
    }

    // ---- epilogue ----
    const int gn0 = bn + wnb + 2 * tig;
    #pragma unroll
    for (int mt = 0; mt < 2; mt++) {
        #pragma unroll
        for (int half = 0; half < 2; half++) {
            int m = bm + wmb + 16 * mt + gid + 8 * half;
            float bv = (EPI == 3) ? 0.f : bias[m];
            float v[8];
            #pragma unroll
            for (int j = 0; j < 4; j++) {
                v[2 * j]     = d[mt][j][2 * half]     + bv;
                v[2 * j + 1] = d[mt][j][2 * half + 1] + bv;
            }
            if (EPI == 1) {
                #pragma unroll
                for (int e = 0; e < 8; e++) {
                    float u = v[e];
                    v[e] = u * 0.5f * (1.f + erff(u * 0.70710678118654752f));
                }
            }
            if (EPI == 2) {
                #pragma unroll
                for (int j = 0; j < 4; j++) {
                    float2 r2 = *(const float2*)&res[(size_t)m * N + gn0 + 8 * j];
                    v[2 * j] += r2.x; v[2 * j + 1] += r2.y;
                }
            }
            if (STATS) {
                float ls = 0.f, ls2 = 0.f;
                #pragma unroll
                for (int e = 0; e < 8; e++) { ls += v[e]; ls2 = fmaf(v[e], v[e], ls2); }
                ls  += __shfl_xor_sync(FULLM, ls, 1);  ls  += __shfl_xor_sync(FULLM, ls, 2);
                ls2 += __shfl_xor_sync(FULLM, ls2, 1); ls2 += __shfl_xor_sync(FULLM, ls2, 2);
                if (tig == 0) {
                    atomicAdd(&g_sums[m], ls);
                    atomicAdd(&g_sums[192 + m], ls2);
                }
            }
            if (EPI == 3) {
                #pragma unroll
                for (int j = 0; j < 4; j++) {
                    atomicAdd(&out[(size_t)m * N + gn0 + 8 * j],     v[2 * j]);
                    atomicAdd(&out[(size_t)m * N + gn0 + 8 * j + 1], v[2 * j + 1]);
                }
            } else if (!OUTNCO) {
                #pragma unroll
                for (int j = 0; j < 4; j++)
                    *(float2*)&out[(size_t)m * N + gn0 + 8 * j] = make_float2(v[2 * j], v[2 * j + 1]);
            } else {
                #pragma unroll
                for (int j = 0; j < 4; j++) {
                    out[(size_t)(gn0 + 8 * j)     * Co + m] = v[2 * j];
                    out[(size_t)(gn0 + 8 * j + 1) * Co + m] = v[2 * j + 1];
                }
            }
        }
    }
}

// ---------------- 3D neighborhood attention (tiled, fp16 K/V in smem) ---------
__global__ void __launch_bounds__(256) attn_kernel(const float* __restrict__ qkv,
                                                   float* __restrict__ o) {
    extern __shared__ __align__(16) half2 sKV[];   // sK[8192] then sV[8192]
    half2* sK = sKV;
    half2* sV = sKV + 8192;

    const int tile = blockIdx.x, head = blockIdx.y;
    const int Td = ((tile >> 4) & 3) * 4, Th = ((tile >> 2) & 3) * 4, Tw = (tile & 3) * 4;
    const int Bd = min(max(Td - 2, 0), 8);
    const int Bh = min(max(Th - 2, 0), 8);
    const int Bw = min(max(Tw - 2, 0), 8);

    const int tid = threadIdx.x;

    #pragma unroll
    for (int it = 0; it < 16; it++) {
        int i = tid + it * 256;
        int row = i >> 3, g = i & 7;
        int rd = row >> 6, rh = (row >> 3) & 7, rw = row & 7;
        int gpos = ((Bd + rd) << 8) + ((Bh + rh) << 4) + (Bw + rw);
        const float* base = qkv + (size_t)gpos * 576 + head * 32 + g * 4;
        float4 kv = *(const float4*)(base + 192);
        float4 vv = *(const float4*)(base + 384);
        sK[row * 16 + g * 2]     = __floats2half2_rn(kv.x, kv.y);
        sK[row * 16 + g * 2 + 1] = __floats2half2_rn(kv.z, kv.w);
        sV[row * 16 + g * 2]     = __floats2half2_rn(vv.x, vv.y);
        sV[row * 16 + g * 2 + 1] = __floats2half2_rn(vv.z, vv.w);
    }

    const int quarter = tid & 3, vox = tid >> 2;
    const int aw = vox & 3, ah = (vox >> 2) & 3, ad = vox >> 4;
    const int vd = Td + ad, vh = Th + ah, vw = Tw + aw;
    const int gv = (vd << 8) + (vh << 4) + vw;
    const int ld = min(max(vd - 2, 0), 11) - Bd;
    const int lh = min(max(vh - 2, 0), 11) - Bh;
    const int lw = min(max(vw - 2, 0), 11) - Bw;
    const int rbase = ld * 64 + lh * 8 + lw;
    const int lane = tid & 31;

    float q[8];
    {
        const float* qp = qkv + (size_t)gv * 576 + head * 32 + quarter * 8;
        #pragma unroll
        for (int c = 0; c < 8; c++) q[c] = qp[c] * 0.17677669529663687f;
    }
    __syncthreads();

    float sc[32];
    #pragma unroll
    for (int i = 0; i < 32; i++) sc[i] = -1e30f;

    #pragma unroll
    for (int j = 0; j < 125; j++) {
        const int a = j / 25, b = (j / 5) % 5, c5 = j % 5;
        int row = rbase + a * 64 + b * 8 + c5;
        uint4 kk = *(const uint4*)(sK + row * 16 + quarter * 4);
        float2 f0 = __half22float2(*reinterpret_cast<half2*>(&kk.x));
        float2 f1 = __half22float2(*reinterpret_cast<half2*>(&kk.y));
        float2 f2 = __half22float2(*reinterpret_cast<half2*>(&kk.z));
        float2 f3 = __half22float2(*reinterpret_cast<half2*>(&kk.w));
        float p = q[0] * f0.x;
        p = fmaf(q[1], f0.y, p); p = fmaf(q[2], f1.x, p); p = fmaf(q[3], f1.y, p);
        p = fmaf(q[4], f2.x, p); p = fmaf(q[5], f2.y, p);
        p = fmaf(q[6], f3.x, p); p = fmaf(q[7], f3.y, p);
        p += __shfl_xor_sync(FULLM, p, 1);
        p += __shfl_xor_sync(FULLM, p, 2);
        if ((j & 3) == quarter) sc[j >> 2] = p;
    }

    float mx = -1e30f;
    #pragma unroll
    for (int i = 0; i < 32; i++) mx = fmaxf(mx, sc[i]);
    mx = fmaxf(mx, __shfl_xor_sync(FULLM, mx, 1));
    mx = fmaxf(mx, __shfl_xor_sync(FULLM, mx, 2));
    float tot = 0.f;
    #pragma unroll
    for (int i = 0; i < 32; i++) { sc[i] = __expf(sc[i] - mx); tot += sc[i]; }
    tot += __shfl_xor_sync(FULLM, tot, 1);
    tot += __shfl_xor_sync(FULLM, tot, 2);
    float inv = 1.f / tot;

    float o8[8] = {0.f, 0.f, 0.f, 0.f, 0.f, 0.f, 0.f, 0.f};
    #pragma unroll
    for (int j = 0; j < 125; j++) {
        const int a = j / 25, b = (j / 5) % 5, c5 = j % 5;
        float p = __shfl_sync(FULLM, sc[j >> 2], (lane & ~3) | (j & 3));
        int row = rbase + a * 64 + b * 8 + c5;
        uint4 vvp = *(const uint4*)(sV + row * 16 + quarter * 4);
        float2 f0 = __half22float2(*reinterpret_cast<half2*>(&vvp.x));
        float2 f1 = __half22float2(*reinterpret_cast<half2*>(&vvp.y));
        float2 f2 = __half22float2(*reinterpret_cast<half2*>(&vvp.z));
        float2 f3 = __half22float2(*reinterpret_cast<half2*>(&vvp.w));
        o8[0] = fmaf(p, f0.x, o8[0]); o8[1] = fmaf(p, f0.y, o8[1]);
        o8[2] = fmaf(p, f1.x, o8[2]); o8[3] = fmaf(p, f1.y, o8[3]);
        o8[4] = fmaf(p, f2.x, o8[4]); o8[5] = fmaf(p, f2.y, o8[5]);
        o8[6] = fmaf(p, f3.x, o8[6]); o8[7] = fmaf(p, f3.y, o8[7]);
    }
    float* op = o + (size_t)gv * 192 + head * 32 + quarter * 8;
    #pragma unroll
    for (int c = 0; c < 8; c++) op[c] = o8[c] * inv;
}

// ---------------- orchestration ----------------------------------------------
extern "C" void kernel_launch(void* const* d_in, const int* in_sizes, int n_in,
                              void* d_out, int out_size) {
    const float* x      = (const float*)d_in[0];
    const float* scale1 = (const float*)d_in[1];
    const float* n1_w1  = (const float*)d_in[2];
    const float* n1_b1  = (const float*)d_in[3];
    const float* n1_w2  = (const float*)d_in[4];
    const float* n1_b2  = (const float*)d_in[5];
    const float* qkv_w  = (const float*)d_in[6];
    const float* qkv_b  = (const float*)d_in[7];
    const float* proj_w = (const float*)d_in[8];
    const float* proj_b = (const float*)d_in[9];
    const float* scale2 = (const float*)d_in[10];
    const float* n2_w1  = (const float*)d_in[11];
    const float* n2_b1  = (const float*)d_in[12];
    const float* n2_w2  = (const float*)d_in[13];
    const float* n2_b2  = (const float*)d_in[14];
    const float* mlp_w1 = (const float*)d_in[15];
    const float* mlp_b1 = (const float*)d_in[16];
    const float* mlp_w2 = (const float*)d_in[17];
    const float* mlp_b2 = (const float*)d_in[18];
    float* out = (float*)d_out;

    float *qkv, *ob, *x2, *mb;
    cudaGetSymbolAddress((void**)&qkv, g_qkv);
    cudaGetSymbolAddress((void**)&ob,  g_o);
    cudaGetSymbolAddress((void**)&x2,  g_x2);
    cudaGetSymbolAddress((void**)&mb,  g_m);

    cudaFuncSetAttribute(attn_kernel, cudaFuncAttributeMaxDynamicSharedMemorySize, 65536);

    // ---- stage A ----
    colstats_kernel<<<192, 256>>>(x);
    gamma1_kernel<<<24, 128>>>(n1_w1, n1_b1);
    gamma2_kernel<<<12, 128>>>(n1_w2, n1_b2, scale1);   // zeroes g_sums

    // qkv: (576,192)@(192,4096) -> (4096,576) pos-major; 576 blocks
    gemm_kernel<192, 192, false, 0, true, false, true><<<dim3(64, 9), 128>>>(
        qkv_w, x, qkv_b, nullptr, qkv, 576, NPOS);

    // attention -> O (4096,192) pos-major
    attn_kernel<<<dim3(64, 6), 256, 65536>>>(qkv, ob);

    // proj + residual + fused stage-B colstats: x2 (C,N); 192 blocks
    gemm_kernel<192, 192, true, 2, false, true, false><<<dim3(64, 3), 128>>>(
        proj_w, ob, proj_b, x, x2, 192, NPOS);

    // ---- stage B ----
    gamma1_kernel<<<24, 128>>>(n2_w1, n2_b1);
    gamma2_kernel<<<12, 128>>>(n2_w2, n2_b2, scale2);   // zeroes g_sums

    // mlp1 + gelu: (768,192)@(192,4096) -> (768,4096); 768 blocks
    gemm_kernel<192, 192, false, 1, true, false, false><<<dim3(64, 12), 128>>>(
        mlp_w1, x2, mlp_b1, nullptr, mb, 768, NPOS);

    // mlp2 split-K x4: init out = x2 + bias, then atomic-accumulate partials
    initout_kernel<<<768, 256>>>(x2, mlp_b2, out);
    gemm_kernel<192, 768, false, 3, false, false, false><<<dim3(64, 3, 4), 128>>>(
        mlp_w2, mb, mlp_b2, x2, out, 192, NPOS);
}

// round 9
// speedup vs baseline: 1.7636x; 1.2209x over previous
#include <cuda_runtime.h>
#include <cuda_fp16.h>
#include <cuda_bf16.h>
#include <math.h>

#define NPOS 4096
#define FULLM 0xffffffffu

// ---------------- scratch (static device globals; no allocation) -------------
__device__ float g_qkv[NPOS * 576];            // (pos, 576) pos-major fp32
__device__ float g_x2 [192 * NPOS];            // (C, pos) fp32
__device__ float g_sums[2 * 192];              // per-channel sum / sumsq (zero-init)
__device__ float g_mult[192];                  // scale*gamma/rms
__device__ float g_h[384];                     // norm-MLP hidden
// bf16 big/small pairs
__device__ __nv_bfloat16 g_wb [768 * 192];     // current W big   (reused per GEMM; mlp_w2 is 192x768 = same size)
__device__ __nv_bfloat16 g_wsm[768 * 192];     // current W small
__device__ __nv_bfloat16 g_xb [192 * NPOS], g_xs [192 * NPOS];   // x pairs (C,N)
__device__ __nv_bfloat16 g_obb[NPOS * 192], g_obs[NPOS * 192];   // attn out pairs (N,C)
__device__ __nv_bfloat16 g_x2b[192 * NPOS], g_x2s[192 * NPOS];   // x2 pairs (C,N)
__device__ __nv_bfloat16 g_mbb[768 * NPOS], g_mbs[768 * NPOS];   // mlp hidden pairs (C,N)

// ---------------- helpers -----------------------------------------------------
__device__ __forceinline__ unsigned smem_u32(const void* p) {
    return (unsigned)__cvta_generic_to_shared(p);
}
__device__ __forceinline__ void cp16(unsigned dst, const void* src) {
    asm volatile("cp.async.cg.shared.global [%0], [%1], 16;" :: "r"(dst), "l"(src));
}
__device__ __forceinline__ void cp_commit() { asm volatile("cp.async.commit_group;"); }
template <int W> __device__ __forceinline__ void cp_wait() {
    asm volatile("cp.async.wait_group %0;" :: "n"(W));
}
__device__ __forceinline__ void mma_bf16(float* d, const unsigned* a, const unsigned* b) {
    asm volatile(
        "mma.sync.aligned.m16n8k16.row.col.f32.bf16.bf16.f32 "
        "{%0,%1,%2,%3},{%4,%5,%6,%7},{%8,%9},{%0,%1,%2,%3};"
        : "+f"(d[0]), "+f"(d[1]), "+f"(d[2]), "+f"(d[3])
        : "r"(a[0]), "r"(a[1]), "r"(a[2]), "r"(a[3]), "r"(b[0]), "r"(b[1]));
}
__device__ __forceinline__ void ldsm_x2_trans(unsigned& r0, unsigned& r1, unsigned addr) {
    asm volatile("ldmatrix.sync.aligned.m8n8.x2.trans.shared.b16 {%0,%1}, [%2];"
                 : "=r"(r0), "=r"(r1) : "r"(addr));
}
__device__ __forceinline__ void store_pair(__nv_bfloat16* pb, __nv_bfloat16* ps,
                                           size_t idx, float v0, float v1) {
    __nv_bfloat16 b0 = __float2bfloat16_rn(v0), b1 = __float2bfloat16_rn(v1);
    __nv_bfloat16 s0 = __float2bfloat16_rn(v0 - __bfloat162float(b0));
    __nv_bfloat16 s1 = __float2bfloat16_rn(v1 - __bfloat162float(b1));
    *(__nv_bfloat162*)(pb + idx) = __halves2bfloat162(b0, b1);
    *(__nv_bfloat162*)(ps + idx) = __halves2bfloat162(s0, s1);
}

// ---------------- per-channel stats over x + bf16 pair conversion -------------
__global__ void colstats_kernel(const float* __restrict__ x,
                                __nv_bfloat16* __restrict__ xb,
                                __nv_bfloat16* __restrict__ xs) {
    int c = blockIdx.x;
    const float* p = x + c * NPOS;
    float s = 0.f, s2 = 0.f;
    for (int i = threadIdx.x; i < NPOS; i += 256) {
        float v = p[i];
        s += v;
        s2 = fmaf(v, v, s2);
        __nv_bfloat16 b = __float2bfloat16_rn(v);
        xb[c * NPOS + i] = b;
        xs[c * NPOS + i] = __float2bfloat16_rn(v - __bfloat162float(b));
    }
    __shared__ float sh0[256], sh1[256];
    sh0[threadIdx.x] = s; sh1[threadIdx.x] = s2;
    __syncthreads();
    for (int o = 128; o > 0; o >>= 1) {
        if (threadIdx.x < o) {
            sh0[threadIdx.x] += sh0[threadIdx.x + o];
            sh1[threadIdx.x] += sh1[threadIdx.x + o];
        }
        __syncthreads();
    }
    if (threadIdx.x == 0) {
        g_sums[c]       = sh0[0];
        g_sums[192 + c] = sh1[0];
    }
}

// ---------------- norm-MLP layer 1 --------------------------------------------
__global__ void gamma1_kernel(const float* __restrict__ w1, const float* __restrict__ b1) {
    const int warp = threadIdx.x >> 5, lane = threadIdx.x & 31;
    const int ob = blockIdx.x * 16 + warp * 4;
    float a0 = 0.f, a1 = 0.f, a2 = 0.f, a3 = 0.f;
    #pragma unroll
    for (int j = 0; j < 6; j++) {
        float sv = g_sums[lane + j * 32] * (1.0f / 4096.0f);
        a0 = fmaf(sv, w1[(ob + 0) * 192 + lane + j * 32], a0);
        a1 = fmaf(sv, w1[(ob + 1) * 192 + lane + j * 32], a1);
        a2 = fmaf(sv, w1[(ob + 2) * 192 + lane + j * 32], a2);
        a3 = fmaf(sv, w1[(ob + 3) * 192 + lane + j * 32], a3);
    }
    #pragma unroll
    for (int off = 16; off; off >>= 1) {
        a0 += __shfl_xor_sync(FULLM, a0, off);
        a1 += __shfl_xor_sync(FULLM, a1, off);
        a2 += __shfl_xor_sync(FULLM, a2, off);
        a3 += __shfl_xor_sync(FULLM, a3, off);
    }
    if (lane == 0) {
        g_h[ob + 0] = fmaxf(a0 + b1[ob + 0], 0.f);
        g_h[ob + 1] = fmaxf(a1 + b1[ob + 1], 0.f);
        g_h[ob + 2] = fmaxf(a2 + b1[ob + 2], 0.f);
        g_h[ob + 3] = fmaxf(a3 + b1[ob + 3], 0.f);
    }
}

// ---------------- norm-MLP layer 2 -> g_mult; zeroes g_sums -------------------
__global__ void gamma2_kernel(const float* __restrict__ w2, const float* __restrict__ b2,
                              const float* __restrict__ scale) {
    const int warp = threadIdx.x >> 5, lane = threadIdx.x & 31;
    const int ob = blockIdx.x * 16 + warp * 4;
    float a0 = 0.f, a1 = 0.f, a2 = 0.f, a3 = 0.f;
    #pragma unroll
    for (int j = 0; j < 12; j++) {
        float hv = g_h[lane + j * 32];
        a0 = fmaf(hv, w2[(ob + 0) * 384 + lane + j * 32], a0);
        a1 = fmaf(hv, w2[(ob + 1) * 384 + lane + j * 32], a1);
        a2 = fmaf(hv, w2[(ob + 2) * 384 + lane + j * 32], a2);
        a3 = fmaf(hv, w2[(ob + 3) * 384 + lane + j * 32], a3);
    }
    #pragma unroll
    for (int off = 16; off; off >>= 1) {
        a0 += __shfl_xor_sync(FULLM, a0, off);
        a1 += __shfl_xor_sync(FULLM, a1, off);
        a2 += __shfl_xor_sync(FULLM, a2, off);
        a3 += __shfl_xor_sync(FULLM, a3, off);
    }
    if (lane == 0) {
        #pragma unroll
        for (int u = 0; u < 4; u++) {
            float a = (u == 0 ? a0 : u == 1 ? a1 : u == 2 ? a2 : a3) + b2[ob + u];
            float gamma = 1.f / (1.f + expf(-a));
            float rms = sqrtf(g_sums[192 + ob + u] * (1.0f / 4096.0f) + 1e-6f);
            g_mult[ob + u] = scale[ob + u] * gamma / rms;
            g_sums[ob + u] = 0.f;
            g_sums[192 + ob + u] = 0.f;
        }
    }
}

// ---------------- weight split conversion (optionally folds g_mult) -----------
template <bool WS>
__global__ void convw_kernel(const float* __restrict__ W, __nv_bfloat16* __restrict__ wb,
                             __nv_bfloat16* __restrict__ wsm, int CIv, int total) {
    int i = blockIdx.x * 256 + threadIdx.x;
    if (i < total) {
        float v = W[i];
        if (WS) v *= g_mult[i % CIv];
        __nv_bfloat16 b = __float2bfloat16_rn(v);
        wb[i]  = b;
        wsm[i] = __float2bfloat16_rn(v - __bfloat162float(b));
    }
}

// ---------------- out init for split-K: out = res + bias ----------------------
__global__ void initout_kernel(const float* __restrict__ res, const float* __restrict__ bias,
                               float* __restrict__ out) {
    int i = blockIdx.x * 256 + threadIdx.x;
    float4 v = ((const float4*)res)[i];
    float b = bias[i >> 10];
    v.x += b; v.y += b; v.z += b; v.w += b;
    ((float4*)out)[i] = v;
}

// ---------------- GEMM v8: bf16x3 pairs, cp.async 3-stage, ldmatrix.trans -----
// out = epi(W(Co,CIFULL) @ X + bias). Block 64m x 64n, 128 thr (4 warps, 2x2).
// BNMAJ: X pairs in (N,CIFULL) n-major (scalar frags); else (CIFULL,N) k-major
//        (ldmatrix.trans frags). blockIdx.z = K-slice (split-K, kbase=z*CI).
// EPI: 0 none, 1 exact gelu, 2 +res(Co,N). OUTM: 0 fp32 (Co,N), 1 fp32 (N,Co),
// 2 atomicAdd (Co,N). PAIRS: also emit bf16 pair copies (Co,N). WF32 w/ OUTM=0.
template <int CI, int CIFULL, bool BNMAJ, int EPI, bool STATS, int OUTM, bool PAIRS, bool WF32>
__global__ void __launch_bounds__(128)
gemm_kernel(const __nv_bfloat16* __restrict__ Awb, const __nv_bfloat16* __restrict__ Aws,
            const __nv_bfloat16* __restrict__ Bxb, const __nv_bfloat16* __restrict__ Bxs,
            const float* __restrict__ bias, const float* __restrict__ res,
            float* __restrict__ out, __nv_bfloat16* __restrict__ pb,
            __nv_bfloat16* __restrict__ ps, int Co, int N) {
    constexpr int NK = CI / 16;
    constexpr int BW = BNMAJ ? (64 * 12) : (16 * 36);   // uint words per B buffer
    __shared__ uint sA[3][2][64 * 12];
    __shared__ uint sB[3][2][BW];

    const int bn = blockIdx.x * 64;
    const int bm = blockIdx.y * 64;
    const int kbase = blockIdx.z * CI;
    const int tid = threadIdx.x;
    const int warp = tid >> 5, lane = tid & 31;
    const int gid = lane >> 2, tig = lane & 3;
    const int wmb = (warp >> 1) * 32;
    const int wnb = (warp & 1) * 32;

    auto stage = [&](int t, int st) {
        const int kk = kbase + t * 16;
        {   // A: 64 rows x 32B = 128 chunks of 16B
            int row = tid >> 1, ch = tid & 1;
            size_t go = (size_t)(bm + row) * CIFULL + kk + ch * 8;
            cp16(smem_u32(&sA[st][0][row * 12 + ch * 4]), Awb + go);
            cp16(smem_u32(&sA[st][1][row * 12 + ch * 4]), Aws + go);
        }
        if (BNMAJ) {
            int row = tid >> 1, ch = tid & 1;
            size_t go = (size_t)(bn + row) * CIFULL + kk + ch * 8;
            cp16(smem_u32(&sB[st][0][row * 12 + ch * 4]), Bxb + go);
            cp16(smem_u32(&sB[st][1][row * 12 + ch * 4]), Bxs + go);
        } else {
            int row = tid >> 3, ch = tid & 7;   // 16 rows x 128B
            size_t go = (size_t)(kk + row) * N + bn + ch * 8;
            cp16(smem_u32((char*)&sB[st][0][0] + row * 144 + ch * 16), Bxb + go);
            cp16(smem_u32((char*)&sB[st][1][0] + row * 144 + ch * 16), Bxs + go);
        }
        cp_commit();
    };

    float d[2][4][4];
    #pragma unroll
    for (int mt = 0; mt < 2; mt++)
        #pragma unroll
        for (int j = 0; j < 4; j++)
            #pragma unroll
            for (int e = 0; e < 4; e++) d[mt][j][e] = 0.f;

    stage(0, 0);
    stage(1, 1);

    #pragma unroll 1
    for (int t = 0; t < NK; t++) {
        const int st = t % 3;
        if (t == NK - 1) cp_wait<0>(); else cp_wait<1>();
        __syncthreads();

        unsigned Ab[2][4], As[2][4];
        #pragma unroll
        for (int mt = 0; mt < 2; mt++) {
            int m0 = wmb + 16 * mt + gid;
            Ab[mt][0] = sA[st][0][m0 * 12 + tig];
            Ab[mt][1] = sA[st][0][(m0 + 8) * 12 + tig];
            Ab[mt][2] = sA[st][0][m0 * 12 + tig + 4];
            Ab[mt][3] = sA[st][0][(m0 + 8) * 12 + tig + 4];
            As[mt][0] = sA[st][1][m0 * 12 + tig];
            As[mt][1] = sA[st][1][(m0 + 8) * 12 + tig];
            As[mt][2] = sA[st][1][m0 * 12 + tig + 4];
            As[mt][3] = sA[st][1][(m0 + 8) * 12 + tig + 4];
        }
        #pragma unroll
        for (int j = 0; j < 4; j++) {
            unsigned Bb[2], Bs[2];
            if (BNMAJ) {
                int n0 = wnb + 8 * j + gid;
                Bb[0] = sB[st][0][n0 * 12 + tig];
                Bb[1] = sB[st][0][n0 * 12 + tig + 4];
                Bs[0] = sB[st][1][n0 * 12 + tig];
                Bs[1] = sB[st][1][n0 * 12 + tig + 4];
            } else {
                int boff = ((lane & 15) * 72 + wnb + 8 * j) * 2;
                ldsm_x2_trans(Bb[0], Bb[1], smem_u32((char*)&sB[st][0][0] + boff));
                ldsm_x2_trans(Bs[0], Bs[1], smem_u32((char*)&sB[st][1][0] + boff));
            }
            #pragma unroll
            for (int mt = 0; mt < 2; mt++) {
                mma_bf16(d[mt][j], Ab[mt], Bb);
                mma_bf16(d[mt][j], As[mt], Bb);
                mma_bf16(d[mt][j], Ab[mt], Bs);
            }
        }
        if (t + 2 < NK) stage(t + 2, (t + 2) % 3);
    }

    // ---- epilogue ----
    const int gn0 = bn + wnb + 2 * tig;
    #pragma unroll
    for (int mt = 0; mt < 2; mt++) {
        #pragma unroll
        for (int half = 0; half < 2; half++) {
            int m = bm + wmb + 16 * mt + gid + 8 * half;
            float bv = (OUTM == 2) ? 0.f : bias[m];
            float v[8];
            #pragma unroll
            for (int j = 0; j < 4; j++) {
                v[2 * j]     = d[mt][j][2 * half]     + bv;
                v[2 * j + 1] = d[mt][j][2 * half + 1] + bv;
            }
            if (EPI == 1) {
                #pragma unroll
                for (int e = 0; e < 8; e++) {
                    float u = v[e];
                    v[e] = u * 0.5f * (1.f + erff(u * 0.70710678118654752f));
                }
            }
            if (EPI == 2) {
                #pragma unroll
                for (int j = 0; j < 4; j++) {
                    float2 r2 = *(const float2*)&res[(size_t)m * N + gn0 + 8 * j];
                    v[2 * j] += r2.x; v[2 * j + 1] += r2.y;
                }
            }
            if (STATS) {
                float ls = 0.f, ls2 = 0.f;
                #pragma unroll
                for (int e = 0; e < 8; e++) { ls += v[e]; ls2 = fmaf(v[e], v[e], ls2); }
                ls  += __shfl_xor_sync(FULLM, ls, 1);  ls  += __shfl_xor_sync(FULLM, ls, 2);
                ls2 += __shfl_xor_sync(FULLM, ls2, 1); ls2 += __shfl_xor_sync(FULLM, ls2, 2);
                if (tig == 0) {
                    atomicAdd(&g_sums[m], ls);
                    atomicAdd(&g_sums[192 + m], ls2);
                }
            }
            if (PAIRS) {
                #pragma unroll
                for (int j = 0; j < 4; j++)
                    store_pair(pb, ps, (size_t)m * N + gn0 + 8 * j, v[2 * j], v[2 * j + 1]);
            }
            if (OUTM == 2) {
                #pragma unroll
                for (int j = 0; j < 4; j++) {
                    atomicAdd(&out[(size_t)m * N + gn0 + 8 * j],     v[2 * j]);
                    atomicAdd(&out[(size_t)m * N + gn0 + 8 * j + 1], v[2 * j + 1]);
                }
            } else if (OUTM == 1) {
                #pragma unroll
                for (int j = 0; j < 4; j++) {
                    out[(size_t)(gn0 + 8 * j)     * Co + m] = v[2 * j];
                    out[(size_t)(gn0 + 8 * j + 1) * Co + m] = v[2 * j + 1];
                }
            } else if (WF32) {
                #pragma unroll
                for (int j = 0; j < 4; j++)
                    *(float2*)&out[(size_t)m * N + gn0 + 8 * j] = make_float2(v[2 * j], v[2 * j + 1]);
            }
        }
    }
}

// ---------------- 3D neighborhood attention (tiled, fp16 K/V in smem) ---------
__global__ void __launch_bounds__(256) attn_kernel(const float* __restrict__ qkv,
                                                   __nv_bfloat16* __restrict__ obb,
                                                   __nv_bfloat16* __restrict__ obs) {
    extern __shared__ __align__(16) half2 sKV[];   // sK[8192] then sV[8192]
    half2* sK = sKV;
    half2* sV = sKV + 8192;

    const int tile = blockIdx.x, head = blockIdx.y;
    const int Td = ((tile >> 4) & 3) * 4, Th = ((tile >> 2) & 3) * 4, Tw = (tile & 3) * 4;
    const int Bd = min(max(Td - 2, 0), 8);
    const int Bh = min(max(Th - 2, 0), 8);
    const int Bw = min(max(Tw - 2, 0), 8);

    const int tid = threadIdx.x;

    #pragma unroll
    for (int it = 0; it < 16; it++) {
        int i = tid + it * 256;
        int row = i >> 3, g = i & 7;
        int rd = row >> 6, rh = (row >> 3) & 7, rw = row & 7;
        int gpos = ((Bd + rd) << 8) + ((Bh + rh) << 4) + (Bw + rw);
        const float* base = qkv + (size_t)gpos * 576 + head * 32 + g * 4;
        float4 kv = *(const float4*)(base + 192);
        float4 vv = *(const float4*)(base + 384);
        sK[row * 16 + g * 2]     = __floats2half2_rn(kv.x, kv.y);
        sK[row * 16 + g * 2 + 1] = __floats2half2_rn(kv.z, kv.w);
        sV[row * 16 + g * 2]     = __floats2half2_rn(vv.x, vv.y);
        sV[row * 16 + g * 2 + 1] = __floats2half2_rn(vv.z, vv.w);
    }

    const int quarter = tid & 3, vox = tid >> 2;
    const int aw = vox & 3, ah = (vox >> 2) & 3, ad = vox >> 4;
    const int vd = Td + ad, vh = Th + ah, vw = Tw + aw;
    const int gv = (vd << 8) + (vh << 4) + vw;
    const int ld = min(max(vd - 2, 0), 11) - Bd;
    const int lh = min(max(vh - 2, 0), 11) - Bh;
    const int lw = min(max(vw - 2, 0), 11) - Bw;
    const int rbase = ld * 64 + lh * 8 + lw;
    const int lane = tid & 31;

    float q[8];
    {
        const float* qp = qkv + (size_t)gv * 576 + head * 32 + quarter * 8;
        #pragma unroll
        for (int c = 0; c < 8; c++) q[c] = qp[c] * 0.17677669529663687f;
    }
    __syncthreads();

    float sc[32];
    #pragma unroll
    for (int i = 0; i < 32; i++) sc[i] = -1e30f;

    #pragma unroll
    for (int j = 0; j < 125; j++) {
        const int a = j / 25, b = (j / 5) % 5, c5 = j % 5;
        int row = rbase + a * 64 + b * 8 + c5;
        uint4 kk = *(const uint4*)(sK + row * 16 + quarter * 4);
        float2 f0 = __half22float2(*reinterpret_cast<half2*>(&kk.x));
        float2 f1 = __half22float2(*reinterpret_cast<half2*>(&kk.y));
        float2 f2 = __half22float2(*reinterpret_cast<half2*>(&kk.z));
        float2 f3 = __half22float2(*reinterpret_cast<half2*>(&kk.w));
        float p = q[0] * f0.x;
        p = fmaf(q[1], f0.y, p); p = fmaf(q[2], f1.x, p); p = fmaf(q[3], f1.y, p);
        p = fmaf(q[4], f2.x, p); p = fmaf(q[5], f2.y, p);
        p = fmaf(q[6], f3.x, p); p = fmaf(q[7], f3.y, p);
        p += __shfl_xor_sync(FULLM, p, 1);
        p += __shfl_xor_sync(FULLM, p, 2);
        if ((j & 3) == quarter) sc[j >> 2] = p;
    }

    float mx = -1e30f;
    #pragma unroll
    for (int i = 0; i < 32; i++) mx = fmaxf(mx, sc[i]);
    mx = fmaxf(mx, __shfl_xor_sync(FULLM, mx, 1));
    mx = fmaxf(mx, __shfl_xor_sync(FULLM, mx, 2));
    float tot = 0.f;
    #pragma unroll
    for (int i = 0; i < 32; i++) { sc[i] = __expf(sc[i] - mx); tot += sc[i]; }
    tot += __shfl_xor_sync(FULLM, tot, 1);
    tot += __shfl_xor_sync(FULLM, tot, 2);
    float inv = 1.f / tot;

    float o8[8] = {0.f, 0.f, 0.f, 0.f, 0.f, 0.f, 0.f, 0.f};
    #pragma unroll
    for (int j = 0; j < 125; j++) {
        const int a = j / 25, b = (j / 5) % 5, c5 = j % 5;
        float p = __shfl_sync(FULLM, sc[j >> 2], (lane & ~3) | (j & 3));
        int row = rbase + a * 64 + b * 8 + c5;
        uint4 vvp = *(const uint4*)(sV + row * 16 + quarter * 4);
        float2 f0 = __half22float2(*reinterpret_cast<half2*>(&vvp.x));
        float2 f1 = __half22float2(*reinterpret_cast<half2*>(&vvp.y));
        float2 f2 = __half22float2(*reinterpret_cast<half2*>(&vvp.z));
        float2 f3 = __half22float2(*reinterpret_cast<half2*>(&vvp.w));
        o8[0] = fmaf(p, f0.x, o8[0]); o8[1] = fmaf(p, f0.y, o8[1]);
        o8[2] = fmaf(p, f1.x, o8[2]); o8[3] = fmaf(p, f1.y, o8[3]);
        o8[4] = fmaf(p, f2.x, o8[4]); o8[5] = fmaf(p, f2.y, o8[5]);
        o8[6] = fmaf(p, f3.x, o8[6]); o8[7] = fmaf(p, f3.y, o8[7]);
    }
    size_t ob0 = (size_t)gv * 192 + head * 32 + quarter * 8;
    #pragma unroll
    for (int c = 0; c < 4; c++)
        store_pair(obb, obs, ob0 + 2 * c, o8[2 * c] * inv, o8[2 * c + 1] * inv);
}

// ---------------- orchestration ----------------------------------------------
extern "C" void kernel_launch(void* const* d_in, const int* in_sizes, int n_in,
                              void* d_out, int out_size) {
    const float* x      = (const float*)d_in[0];
    const float* scale1 = (const float*)d_in[1];
    const float* n1_w1  = (const float*)d_in[2];
    const float* n1_b1  = (const float*)d_in[3];
    const float* n1_w2  = (const float*)d_in[4];
    const float* n1_b2  = (const float*)d_in[5];
    const float* qkv_w  = (const float*)d_in[6];
    const float* qkv_b  = (const float*)d_in[7];
    const float* proj_w = (const float*)d_in[8];
    const float* proj_b = (const float*)d_in[9];
    const float* scale2 = (const float*)d_in[10];
    const float* n2_w1  = (const float*)d_in[11];
    const float* n2_b1  = (const float*)d_in[12];
    const float* n2_w2  = (const float*)d_in[13];
    const float* n2_b2  = (const float*)d_in[14];
    const float* mlp_w1 = (const float*)d_in[15];
    const float* mlp_b1 = (const float*)d_in[16];
    const float* mlp_w2 = (const float*)d_in[17];
    const float* mlp_b2 = (const float*)d_in[18];
    float* out = (float*)d_out;

    float *qkv, *x2;
    __nv_bfloat16 *wb, *wsm, *xb, *xs, *obb, *obs, *x2b, *x2s, *mbb, *mbs;
    cudaGetSymbolAddress((void**)&qkv, g_qkv);
    cudaGetSymbolAddress((void**)&x2,  g_x2);
    cudaGetSymbolAddress((void**)&wb,  g_wb);
    cudaGetSymbolAddress((void**)&wsm, g_wsm);
    cudaGetSymbolAddress((void**)&xb,  g_xb);
    cudaGetSymbolAddress((void**)&xs,  g_xs);
    cudaGetSymbolAddress((void**)&obb, g_obb);
    cudaGetSymbolAddress((void**)&obs, g_obs);
    cudaGetSymbolAddress((void**)&x2b, g_x2b);
    cudaGetSymbolAddress((void**)&x2s, g_x2s);
    cudaGetSymbolAddress((void**)&mbb, g_mbb);
    cudaGetSymbolAddress((void**)&mbs, g_mbs);

    cudaFuncSetAttribute(attn_kernel, cudaFuncAttributeMaxDynamicSharedMemorySize, 65536);

    // ---- stage A ----
    colstats_kernel<<<192, 256>>>(x, xb, xs);           // also emits x bf16 pairs
    gamma1_kernel<<<24, 128>>>(n1_w1, n1_b1);
    gamma2_kernel<<<12, 128>>>(n1_w2, n1_b2, scale1);   // zeroes g_sums
    convw_kernel<true><<<432, 256>>>(qkv_w, wb, wsm, 192, 576 * 192);

    // qkv: (576,192)@(192,4096) -> (4096,576) fp32 pos-major
    gemm_kernel<192, 192, false, 0, false, 1, false, false><<<dim3(64, 9), 128>>>(
        wb, wsm, xb, xs, qkv_b, nullptr, qkv, nullptr, nullptr, 576, NPOS);

    // attention -> ob bf16 pairs (N,C)
    attn_kernel<<<dim3(64, 6), 256, 65536>>>(qkv, obb, obs);

    // proj + residual + stage-B stats; writes x2 fp32 + bf16 pairs
    convw_kernel<false><<<144, 256>>>(proj_w, wb, wsm, 192, 192 * 192);
    gemm_kernel<192, 192, true, 2, true, 0, true, true><<<dim3(64, 3), 128>>>(
        wb, wsm, obb, obs, proj_b, x, x2, x2b, x2s, 192, NPOS);

    // ---- stage B ----
    gamma1_kernel<<<24, 128>>>(n2_w1, n2_b1);
    gamma2_kernel<<<12, 128>>>(n2_w2, n2_b2, scale2);   // zeroes g_sums
    convw_kernel<true><<<576, 256>>>(mlp_w1, wb, wsm, 192, 768 * 192);

    // mlp1 + gelu -> mb bf16 pairs only
    gemm_kernel<192, 192, false, 1, false, 0, true, false><<<dim3(64, 12), 128>>>(
        wb, wsm, x2b, x2s, mlp_b1, nullptr, nullptr, mbb, mbs, 768, NPOS);

    // mlp2 split-K x4: init out = x2 + bias, then atomic-accumulate
    convw_kernel<false><<<576, 256>>>(mlp_w2, wb, wsm, 768, 192 * 768);
    initout_kernel<<<768, 256>>>(x2, mlp_b2, out);
    gemm_kernel<192, 768, false, 0, false, 2, false, false><<<dim3(64, 3, 4), 128>>>(
        wb, wsm, mbb, mbs, mlp_b2, nullptr, out, nullptr, nullptr, 192, NPOS);
}